// round 6
// baseline (speedup 1.0000x reference)
#include <cuda_runtime.h>
#include <math.h>

#define BATCH 256
#define TLEN  256
#define HID   256
#define G3    768   // 3*H

// Scratch (device globals — no allocation)
__device__ float g_gx0[BATCH * TLEN * G3];   // layer0 precomputed gi x-part (+b_ih)
__device__ float g_gx1[BATCH * TLEN * G3];   // layer1
__device__ float g_h0[2][BATCH * HID];       // double-buffered hidden state, parity = t&1
__device__ float g_h1[2][BATCH * HID];

// ---------------------------------------------------------------------------
// init: copy initial hidden states into both parity buffers
// ---------------------------------------------------------------------------
__global__ void init_state(const float* __restrict__ hx0, const float* __restrict__ hx1) {
    int i = blockIdx.x * blockDim.x + threadIdx.x;
    if (i < BATCH * HID) {
        g_h0[0][i] = hx0[i];
        g_h0[1][i] = hx0[i];
        g_h1[0][i] = hx1[i];
        g_h1[1][i] = hx1[i];
    }
}

// ---------------------------------------------------------------------------
// Precompute: gx[m][j] = mask[m] * sum_k x[m][k]*W[j][k] + b_ih[j]
//   m = b*T + t,  j in [0,768),  K = 256 (x-part columns of W_ih, row stride 512)
//   layer0 mask: dx_layer_zero[b][t];  layer1 mask: dx[b][0][t]
// CTA tile 128(m) x 64(j), K-chunks of 16, 256 threads, 8x4 microtile.
// ---------------------------------------------------------------------------
__global__ __launch_bounds__(256) void precompute_kernel(
    const float* __restrict__ x, const float* __restrict__ W,
    const float* __restrict__ bias,
    const int* __restrict__ dx, const int* __restrict__ dxlz, int layer)
{
    __shared__ float As[16][128];
    __shared__ float Bs[16][64];

    float* gx = layer ? g_gx1 : g_gx0;
    int mBase = blockIdx.x * 128;
    int jBase = blockIdx.y * 64;
    int tid = threadIdx.x;
    int tmi = tid & 15;     // m subtile index (x8)
    int tji = tid >> 4;     // j subtile index (x4)

    float acc[8][4];
#pragma unroll
    for (int i = 0; i < 8; i++)
#pragma unroll
        for (int j = 0; j < 4; j++) acc[i][j] = 0.0f;

    for (int kk = 0; kk < 256; kk += 16) {
        __syncthreads();
        // stage A (x rows, masked), transposed to [k][m]
#pragma unroll
        for (int i = 0; i < 2; i++) {
            int idx = tid + i * 256;     // 0..511 float4s
            int m   = idx & 127;
            int k4  = idx >> 7;          // 0..3
            int mg  = mBase + m;
            float msk;
            if (layer == 0) msk = (float)dxlz[mg];
            else            msk = (float)dx[((mg >> 8) << 9) + (mg & 255)];
            float4 v = *(const float4*)(x + (size_t)mg * 256 + kk + k4 * 4);
            As[k4 * 4 + 0][m] = v.x * msk;
            As[k4 * 4 + 1][m] = v.y * msk;
            As[k4 * 4 + 2][m] = v.z * msk;
            As[k4 * 4 + 3][m] = v.w * msk;
        }
        // stage B (W_ih rows, x-part cols), transposed to [k][j]
        {
            int j  = tid & 63;
            int k4 = tid >> 6;   // 0..3
            float4 v = *(const float4*)(W + (size_t)(jBase + j) * 512 + kk + k4 * 4);
            Bs[k4 * 4 + 0][j] = v.x;
            Bs[k4 * 4 + 1][j] = v.y;
            Bs[k4 * 4 + 2][j] = v.z;
            Bs[k4 * 4 + 3][j] = v.w;
        }
        __syncthreads();
#pragma unroll
        for (int k = 0; k < 16; k++) {
            float4 a0 = *(const float4*)&As[k][tmi * 8];
            float4 a1 = *(const float4*)&As[k][tmi * 8 + 4];
            float4 bv = *(const float4*)&Bs[k][tji * 4];
            float am[8] = {a0.x, a0.y, a0.z, a0.w, a1.x, a1.y, a1.z, a1.w};
            float bm[4] = {bv.x, bv.y, bv.z, bv.w};
#pragma unroll
            for (int i = 0; i < 8; i++)
#pragma unroll
                for (int j = 0; j < 4; j++) acc[i][j] += am[i] * bm[j];
        }
    }

    float4 bb = *(const float4*)(bias + jBase + tji * 4);
#pragma unroll
    for (int i = 0; i < 8; i++) {
        int m = mBase + tmi * 8 + i;
        float4 o;
        o.x = acc[i][0] + bb.x;
        o.y = acc[i][1] + bb.y;
        o.z = acc[i][2] + bb.z;
        o.w = acc[i][3] + bb.w;
        *(float4*)(gx + (size_t)m * G3 + jBase + tji * 4) = o;
    }
}

// ---------------------------------------------------------------------------
// Step kernel: one layer of one timestep.
//   accI[j] = dot(hA[b], Wih[j][256:])     (scaled by mA[b] afterwards)
//   accH[j] = dot(hB[b], Whh[j])           (scaled by fB[b] afterwards)
//   gi = gx[b,t,j] + mA*accI ; gh = b_hh[j] + fB*accH
//   r=sig, z=sig, n=tanh(giN + r*ghN); hUsed = hB*fB
//   hnew = (1-z)*n + z*hUsed; res = bypass ? hUsed : hnew
// Grid (8,16): CTA tile 32b x 16u (x3 gates). 128 threads, microtile 2b x 2u.
// ---------------------------------------------------------------------------
#define KC 64

__global__ __launch_bounds__(128) void step_kernel(
    int t, int layer,
    const float* __restrict__ Wih, const float* __restrict__ Whh,
    const float* __restrict__ bhh,
    const int* __restrict__ dx, const int* __restrict__ dxlz,
    float* __restrict__ out)
{
    __shared__ float sA[KC][32];          // hA rows, k-major
    __shared__ float sB[KC][32];          // hB rows, k-major
    __shared__ float sWi[3][KC][16];      // Wih h-part rows (u-tile), k-major
    __shared__ float sWh[3][KC][16];      // Whh rows, k-major

    int p  = t & 1;
    int pn = p ^ 1;
    const float* hA   = layer ? g_h0[pn] : g_h1[p];   // layer1 uses freshly written h0
    const float* hB   = layer ? g_h1[p]  : g_h0[p];
    float*       hOut = layer ? g_h1[pn] : g_h0[pn];
    const float* gx   = layer ? g_gx1    : g_gx0;

    int bTile = blockIdx.x * 32;
    int uTile = blockIdx.y * 16;
    int tid = threadIdx.x;
    int tb = tid & 15;    // 16 b-threads (x2 rows)
    int tu = tid >> 4;    // 8 u-threads (x2 cols)

    float accI[2][2][3];
    float accH[2][2][3];
#pragma unroll
    for (int a = 0; a < 2; a++)
#pragma unroll
        for (int b = 0; b < 2; b++)
#pragma unroll
            for (int g = 0; g < 3; g++) { accI[a][b][g] = 0.0f; accH[a][b][g] = 0.0f; }

    for (int kc = 0; kc < 256; kc += KC) {
        __syncthreads();
        // stage h rows (transpose to k-major)
#pragma unroll
        for (int i = 0; i < 4; i++) {
            int idx = tid + i * 128;   // 0..511 float4s
            int bb  = idx & 31;
            int k4  = idx >> 5;        // 0..15
            float4 v = *(const float4*)(hA + (size_t)(bTile + bb) * HID + kc + k4 * 4);
            sA[k4 * 4 + 0][bb] = v.x; sA[k4 * 4 + 1][bb] = v.y;
            sA[k4 * 4 + 2][bb] = v.z; sA[k4 * 4 + 3][bb] = v.w;
            float4 w = *(const float4*)(hB + (size_t)(bTile + bb) * HID + kc + k4 * 4);
            sB[k4 * 4 + 0][bb] = w.x; sB[k4 * 4 + 1][bb] = w.y;
            sB[k4 * 4 + 2][bb] = w.z; sB[k4 * 4 + 3][bb] = w.w;
        }
        // stage weights for the 16-u tile, all 3 gates, both matrices
#pragma unroll
        for (int i = 0; i < 6; i++) {
            int idx = tid + i * 128;       // 0..767 float4s
            int ul  = idx & 15;
            int k4  = (idx >> 4) & 15;
            int g   = idx >> 8;            // 0..2
            int row = g * HID + uTile + ul;
            float4 v = *(const float4*)(Wih + (size_t)row * 512 + 256 + kc + k4 * 4);
            sWi[g][k4 * 4 + 0][ul] = v.x; sWi[g][k4 * 4 + 1][ul] = v.y;
            sWi[g][k4 * 4 + 2][ul] = v.z; sWi[g][k4 * 4 + 3][ul] = v.w;
            float4 w = *(const float4*)(Whh + (size_t)row * HID + kc + k4 * 4);
            sWh[g][k4 * 4 + 0][ul] = w.x; sWh[g][k4 * 4 + 1][ul] = w.y;
            sWh[g][k4 * 4 + 2][ul] = w.z; sWh[g][k4 * 4 + 3][ul] = w.w;
        }
        __syncthreads();
#pragma unroll
        for (int k = 0; k < KC; k++) {
            float2 a  = *(const float2*)&sA[k][tb * 2];
            float2 hb = *(const float2*)&sB[k][tb * 2];
#pragma unroll
            for (int g = 0; g < 3; g++) {
                float2 wi = *(const float2*)&sWi[g][k][tu * 2];
                float2 wh = *(const float2*)&sWh[g][k][tu * 2];
                accI[0][0][g] += a.x * wi.x;
                accI[0][1][g] += a.x * wi.y;
                accI[1][0][g] += a.y * wi.x;
                accI[1][1][g] += a.y * wi.y;
                accH[0][0][g] += hb.x * wh.x;
                accH[0][1][g] += hb.x * wh.y;
                accH[1][0][g] += hb.y * wh.x;
                accH[1][1][g] += hb.y * wh.y;
            }
        }
    }

    // epilogue: masks, gates, bypass, writes
#pragma unroll
    for (int bi = 0; bi < 2; bi++) {
        int b = bTile + tb * 2 + bi;
        float mA, fB; int byp;
        if (layer == 0) {
            int b0  = dxlz[b * TLEN + t];
            int dd0 = (t > 0) ? dx[(b * 2) * TLEN + t - 1] : 0;
            mA = (float)dd0; fB = 1.0f - (float)dd0; byp = (b0 + dd0 == 0);
        } else {
            int b1  = dx[(b * 2) * TLEN + t];
            int dd1 = (t > 0) ? dx[(b * 2 + 1) * TLEN + t - 1] : 0;
            mA = (float)b1; fB = 1.0f - (float)dd1; byp = (b1 + dd1 == 0);
        }
        const float* gxr = gx + (size_t)(b * TLEN + t) * G3;
#pragma unroll
        for (int ui = 0; ui < 2; ui++) {
            int u = uTile + tu * 2 + ui;
            float hprev = hB[b * HID + u];
            float hUsed = hprev * fB;
            float giR = gxr[u]        + mA * accI[bi][ui][0];
            float giZ = gxr[256 + u]  + mA * accI[bi][ui][1];
            float giN = gxr[512 + u]  + mA * accI[bi][ui][2];
            float ghR = bhh[u]        + fB * accH[bi][ui][0];
            float ghZ = bhh[256 + u]  + fB * accH[bi][ui][1];
            float ghN = bhh[512 + u]  + fB * accH[bi][ui][2];
            float r = 1.0f / (1.0f + expf(-(giR + ghR)));
            float z = 1.0f / (1.0f + expf(-(giZ + ghZ)));
            float n = tanhf(giN + r * ghN);
            float hnew = (1.0f - z) * n + z * hUsed;
            float res = byp ? hUsed : hnew;
            hOut[b * HID + u] = res;
            out[(((size_t)layer * BATCH + b) * TLEN + t) * HID + u] = res;
        }
    }
}

// ---------------------------------------------------------------------------
extern "C" void kernel_launch(void* const* d_in, const int* in_sizes, int n_in,
                              void* d_out, int out_size) {
    const float* x0    = (const float*)d_in[0];
    const float* x1    = (const float*)d_in[1];
    const float* hx0   = (const float*)d_in[2];
    const float* hx1   = (const float*)d_in[3];
    const float* W_ih0 = (const float*)d_in[4];
    const float* W_hh0 = (const float*)d_in[5];
    const float* b_ih0 = (const float*)d_in[6];
    const float* b_hh0 = (const float*)d_in[7];
    const float* W_ih1 = (const float*)d_in[8];
    const float* W_hh1 = (const float*)d_in[9];
    const float* b_ih1 = (const float*)d_in[10];
    const float* b_hh1 = (const float*)d_in[11];
    const int*   dx    = (const int*)d_in[12];
    const int*   dxlz  = (const int*)d_in[13];
    float* out = (float*)d_out;

    init_state<<<256, 256>>>(hx0, hx1);

    dim3 pgrid(512, 12);
    precompute_kernel<<<pgrid, 256>>>(x0, W_ih0, b_ih0, dx, dxlz, 0);
    precompute_kernel<<<pgrid, 256>>>(x1, W_ih1, b_ih1, dx, dxlz, 1);

    dim3 sgrid(8, 16);
    for (int t = 0; t < TLEN; t++) {
        step_kernel<<<sgrid, 128>>>(t, 0, W_ih0, W_hh0, b_hh0, dx, dxlz, out);
        step_kernel<<<sgrid, 128>>>(t, 1, W_ih1, W_hh1, b_hh1, dx, dxlz, out);
    }
}

// round 7
// speedup vs baseline: 1.0020x; 1.0020x over previous
#include <cuda_runtime.h>
#include <math.h>

#define BATCH 256
#define TLEN  256
#define HID   256
#define G3    768   // 3*H

// Scratch (device globals — no allocation)
__device__ float g_gx0[BATCH * TLEN * G3];   // layer0 precomputed gi x-part (+b_ih)
__device__ float g_gx1[BATCH * TLEN * G3];   // layer1
__device__ float g_h0[2][BATCH * HID];       // double-buffered hidden state, parity = t&1
__device__ float g_h1[2][BATCH * HID];

// ---------------------------------------------------------------------------
// init: copy initial hidden states into both parity buffers
// ---------------------------------------------------------------------------
__global__ void init_state(const float* __restrict__ hx0, const float* __restrict__ hx1) {
    int i = blockIdx.x * blockDim.x + threadIdx.x;
    if (i < BATCH * HID) {
        g_h0[0][i] = hx0[i];
        g_h0[1][i] = hx0[i];
        g_h1[0][i] = hx1[i];
        g_h1[1][i] = hx1[i];
    }
}

// ---------------------------------------------------------------------------
// Precompute: gx[m][j] = mask[m] * sum_k x[m][k]*W[j][k] + b_ih[j]
//   m = b*T + t,  j in [0,768),  K = 256 (x-part columns of W_ih, row stride 512)
//   layer0 mask: dx_layer_zero[b][t];  layer1 mask: dx[b][0][t]
// CTA tile 128(m) x 64(j), K-chunks of 16, 256 threads, 8x4 microtile.
// ---------------------------------------------------------------------------
__global__ __launch_bounds__(256) void precompute_kernel(
    const float* __restrict__ x, const float* __restrict__ W,
    const float* __restrict__ bias,
    const int* __restrict__ dx, const int* __restrict__ dxlz, int layer)
{
    __shared__ float As[16][128];
    __shared__ float Bs[16][64];

    float* gx = layer ? g_gx1 : g_gx0;
    int mBase = blockIdx.x * 128;
    int jBase = blockIdx.y * 64;
    int tid = threadIdx.x;
    int tmi = tid & 15;     // m subtile index (x8)
    int tji = tid >> 4;     // j subtile index (x4)

    float acc[8][4];
#pragma unroll
    for (int i = 0; i < 8; i++)
#pragma unroll
        for (int j = 0; j < 4; j++) acc[i][j] = 0.0f;

    for (int kk = 0; kk < 256; kk += 16) {
        __syncthreads();
        // stage A (x rows, masked), transposed to [k][m]
#pragma unroll
        for (int i = 0; i < 2; i++) {
            int idx = tid + i * 256;     // 0..511 float4s
            int m   = idx & 127;
            int k4  = idx >> 7;          // 0..3
            int mg  = mBase + m;
            float msk;
            if (layer == 0) msk = (float)dxlz[mg];
            else            msk = (float)dx[((mg >> 8) << 9) + (mg & 255)];
            float4 v = *(const float4*)(x + (size_t)mg * 256 + kk + k4 * 4);
            As[k4 * 4 + 0][m] = v.x * msk;
            As[k4 * 4 + 1][m] = v.y * msk;
            As[k4 * 4 + 2][m] = v.z * msk;
            As[k4 * 4 + 3][m] = v.w * msk;
        }
        // stage B (W_ih rows, x-part cols), transposed to [k][j]
        {
            int j  = tid & 63;
            int k4 = tid >> 6;   // 0..3
            float4 v = *(const float4*)(W + (size_t)(jBase + j) * 512 + kk + k4 * 4);
            Bs[k4 * 4 + 0][j] = v.x;
            Bs[k4 * 4 + 1][j] = v.y;
            Bs[k4 * 4 + 2][j] = v.z;
            Bs[k4 * 4 + 3][j] = v.w;
        }
        __syncthreads();
#pragma unroll
        for (int k = 0; k < 16; k++) {
            float4 a0 = *(const float4*)&As[k][tmi * 8];
            float4 a1 = *(const float4*)&As[k][tmi * 8 + 4];
            float4 bv = *(const float4*)&Bs[k][tji * 4];
            float am[8] = {a0.x, a0.y, a0.z, a0.w, a1.x, a1.y, a1.z, a1.w};
            float bm[4] = {bv.x, bv.y, bv.z, bv.w};
#pragma unroll
            for (int i = 0; i < 8; i++)
#pragma unroll
                for (int j = 0; j < 4; j++) acc[i][j] += am[i] * bm[j];
        }
    }

    float4 bb = *(const float4*)(bias + jBase + tji * 4);
#pragma unroll
    for (int i = 0; i < 8; i++) {
        int m = mBase + tmi * 8 + i;
        float4 o;
        o.x = acc[i][0] + bb.x;
        o.y = acc[i][1] + bb.y;
        o.z = acc[i][2] + bb.z;
        o.w = acc[i][3] + bb.w;
        *(float4*)(gx + (size_t)m * G3 + jBase + tji * 4) = o;
    }
}

// ---------------------------------------------------------------------------
// Step kernel: one layer of one timestep.
//   accI[j] = dot(hA[b], Wih[j][256:])     (scaled by mA[b] afterwards)
//   accH[j] = dot(hB[b], Whh[j])           (scaled by fB[b] afterwards)
//   gi = gx[b,t,j] + mA*accI ; gh = b_hh[j] + fB*accH
//   r=sig, z=sig, n=tanh(giN + r*ghN); hUsed = hB*fB
//   hnew = (1-z)*n + z*hUsed; res = bypass ? hUsed : hnew
// Grid (8,16): CTA tile 32b x 16u (x3 gates). 128 threads, microtile 2b x 2u.
// ---------------------------------------------------------------------------
#define KC 64

__global__ __launch_bounds__(128) void step_kernel(
    int t, int layer,
    const float* __restrict__ Wih, const float* __restrict__ Whh,
    const float* __restrict__ bhh,
    const int* __restrict__ dx, const int* __restrict__ dxlz,
    float* __restrict__ out)
{
    __shared__ float sA[KC][32];          // hA rows, k-major
    __shared__ float sB[KC][32];          // hB rows, k-major
    __shared__ float sWi[3][KC][16];      // Wih h-part rows (u-tile), k-major
    __shared__ float sWh[3][KC][16];      // Whh rows, k-major

    int p  = t & 1;
    int pn = p ^ 1;
    const float* hA   = layer ? g_h0[pn] : g_h1[p];   // layer1 uses freshly written h0
    const float* hB   = layer ? g_h1[p]  : g_h0[p];
    float*       hOut = layer ? g_h1[pn] : g_h0[pn];
    const float* gx   = layer ? g_gx1    : g_gx0;

    int bTile = blockIdx.x * 32;
    int uTile = blockIdx.y * 16;
    int tid = threadIdx.x;
    int tb = tid & 15;    // 16 b-threads (x2 rows)
    int tu = tid >> 4;    // 8 u-threads (x2 cols)

    float accI[2][2][3];
    float accH[2][2][3];
#pragma unroll
    for (int a = 0; a < 2; a++)
#pragma unroll
        for (int b = 0; b < 2; b++)
#pragma unroll
            for (int g = 0; g < 3; g++) { accI[a][b][g] = 0.0f; accH[a][b][g] = 0.0f; }

    for (int kc = 0; kc < 256; kc += KC) {
        __syncthreads();
        // stage h rows (transpose to k-major)
#pragma unroll
        for (int i = 0; i < 4; i++) {
            int idx = tid + i * 128;   // 0..511 float4s
            int bb  = idx & 31;
            int k4  = idx >> 5;        // 0..15
            float4 v = *(const float4*)(hA + (size_t)(bTile + bb) * HID + kc + k4 * 4);
            sA[k4 * 4 + 0][bb] = v.x; sA[k4 * 4 + 1][bb] = v.y;
            sA[k4 * 4 + 2][bb] = v.z; sA[k4 * 4 + 3][bb] = v.w;
            float4 w = *(const float4*)(hB + (size_t)(bTile + bb) * HID + kc + k4 * 4);
            sB[k4 * 4 + 0][bb] = w.x; sB[k4 * 4 + 1][bb] = w.y;
            sB[k4 * 4 + 2][bb] = w.z; sB[k4 * 4 + 3][bb] = w.w;
        }
        // stage weights for the 16-u tile, all 3 gates, both matrices
#pragma unroll
        for (int i = 0; i < 6; i++) {
            int idx = tid + i * 128;       // 0..767 float4s
            int ul  = idx & 15;
            int k4  = (idx >> 4) & 15;
            int g   = idx >> 8;            // 0..2
            int row = g * HID + uTile + ul;
            float4 v = *(const float4*)(Wih + (size_t)row * 512 + 256 + kc + k4 * 4);
            sWi[g][k4 * 4 + 0][ul] = v.x; sWi[g][k4 * 4 + 1][ul] = v.y;
            sWi[g][k4 * 4 + 2][ul] = v.z; sWi[g][k4 * 4 + 3][ul] = v.w;
            float4 w = *(const float4*)(Whh + (size_t)row * HID + kc + k4 * 4);
            sWh[g][k4 * 4 + 0][ul] = w.x; sWh[g][k4 * 4 + 1][ul] = w.y;
            sWh[g][k4 * 4 + 2][ul] = w.z; sWh[g][k4 * 4 + 3][ul] = w.w;
        }
        __syncthreads();
#pragma unroll
        for (int k = 0; k < KC; k++) {
            float2 a  = *(const float2*)&sA[k][tb * 2];
            float2 hb = *(const float2*)&sB[k][tb * 2];
#pragma unroll
            for (int g = 0; g < 3; g++) {
                float2 wi = *(const float2*)&sWi[g][k][tu * 2];
                float2 wh = *(const float2*)&sWh[g][k][tu * 2];
                accI[0][0][g] += a.x * wi.x;
                accI[0][1][g] += a.x * wi.y;
                accI[1][0][g] += a.y * wi.x;
                accI[1][1][g] += a.y * wi.y;
                accH[0][0][g] += hb.x * wh.x;
                accH[0][1][g] += hb.x * wh.y;
                accH[1][0][g] += hb.y * wh.x;
                accH[1][1][g] += hb.y * wh.y;
            }
        }
    }

    // epilogue: masks, gates, bypass, writes
#pragma unroll
    for (int bi = 0; bi < 2; bi++) {
        int b = bTile + tb * 2 + bi;
        float mA, fB; int byp;
        if (layer == 0) {
            int b0  = dxlz[b * TLEN + t];
            int dd0 = (t > 0) ? dx[(b * 2) * TLEN + t - 1] : 0;
            mA = (float)dd0; fB = 1.0f - (float)dd0; byp = (b0 + dd0 == 0);
        } else {
            int b1  = dx[(b * 2) * TLEN + t];
            int dd1 = (t > 0) ? dx[(b * 2 + 1) * TLEN + t - 1] : 0;
            mA = (float)b1; fB = 1.0f - (float)dd1; byp = (b1 + dd1 == 0);
        }
        const float* gxr = gx + (size_t)(b * TLEN + t) * G3;
#pragma unroll
        for (int ui = 0; ui < 2; ui++) {
            int u = uTile + tu * 2 + ui;
            float hprev = hB[b * HID + u];
            float hUsed = hprev * fB;
            float giR = gxr[u]        + mA * accI[bi][ui][0];
            float giZ = gxr[256 + u]  + mA * accI[bi][ui][1];
            float giN = gxr[512 + u]  + mA * accI[bi][ui][2];
            float ghR = bhh[u]        + fB * accH[bi][ui][0];
            float ghZ = bhh[256 + u]  + fB * accH[bi][ui][1];
            float ghN = bhh[512 + u]  + fB * accH[bi][ui][2];
            float r = 1.0f / (1.0f + expf(-(giR + ghR)));
            float z = 1.0f / (1.0f + expf(-(giZ + ghZ)));
            float n = tanhf(giN + r * ghN);
            float hnew = (1.0f - z) * n + z * hUsed;
            float res = byp ? hUsed : hnew;
            hOut[b * HID + u] = res;
            out[(((size_t)layer * BATCH + b) * TLEN + t) * HID + u] = res;
        }
    }
}

// ---------------------------------------------------------------------------
extern "C" void kernel_launch(void* const* d_in, const int* in_sizes, int n_in,
                              void* d_out, int out_size) {
    const float* x0    = (const float*)d_in[0];
    const float* x1    = (const float*)d_in[1];
    const float* hx0   = (const float*)d_in[2];
    const float* hx1   = (const float*)d_in[3];
    const float* W_ih0 = (const float*)d_in[4];
    const float* W_hh0 = (const float*)d_in[5];
    const float* b_ih0 = (const float*)d_in[6];
    const float* b_hh0 = (const float*)d_in[7];
    const float* W_ih1 = (const float*)d_in[8];
    const float* W_hh1 = (const float*)d_in[9];
    const float* b_ih1 = (const float*)d_in[10];
    const float* b_hh1 = (const float*)d_in[11];
    const int*   dx    = (const int*)d_in[12];
    const int*   dxlz  = (const int*)d_in[13];
    float* out = (float*)d_out;

    init_state<<<256, 256>>>(hx0, hx1);

    dim3 pgrid(512, 12);
    precompute_kernel<<<pgrid, 256>>>(x0, W_ih0, b_ih0, dx, dxlz, 0);
    precompute_kernel<<<pgrid, 256>>>(x1, W_ih1, b_ih1, dx, dxlz, 1);

    dim3 sgrid(8, 16);
    for (int t = 0; t < TLEN; t++) {
        step_kernel<<<sgrid, 128>>>(t, 0, W_ih0, W_hh0, b_hh0, dx, dxlz, out);
        step_kernel<<<sgrid, 128>>>(t, 1, W_ih1, W_hh1, b_hh1, dx, dxlz, out);
    }
}

// round 8
// speedup vs baseline: 1.3067x; 1.3041x over previous
#include <cuda_runtime.h>
#include <math.h>

#define BATCH 256
#define TLEN  256
#define HID   256
#define G3    768   // 3*H
#define NCTA  128

// Scratch (device globals — no allocation)
__device__ float g_gx0[BATCH * TLEN * G3];   // layer0 precomputed gi x-part (+b_ih)
__device__ float g_gx1[BATCH * TLEN * G3];   // layer1
__device__ float g_h0[2][BATCH * HID];       // double-buffered hidden state, parity = t&1
__device__ float g_h1[2][BATCH * HID];
__device__ unsigned g_arrive;
__device__ volatile unsigned g_release;

// ---------------------------------------------------------------------------
// init: copy initial hidden states into both parity buffers, reset barrier
// ---------------------------------------------------------------------------
__global__ void init_state(const float* __restrict__ hx0, const float* __restrict__ hx1) {
    int i = blockIdx.x * blockDim.x + threadIdx.x;
    if (i == 0) { g_arrive = 0u; g_release = 0u; }
    if (i < BATCH * HID) {
        g_h0[0][i] = hx0[i];
        g_h0[1][i] = hx0[i];
        g_h1[0][i] = hx1[i];
        g_h1[1][i] = hx1[i];
    }
}

// ---------------------------------------------------------------------------
// Precompute: gx[m][j] = mask[m] * sum_k x[m][k]*W[j][k] + b_ih[j]   (unchanged)
// ---------------------------------------------------------------------------
__global__ __launch_bounds__(256) void precompute_kernel(
    const float* __restrict__ x, const float* __restrict__ W,
    const float* __restrict__ bias,
    const int* __restrict__ dx, const int* __restrict__ dxlz, int layer)
{
    __shared__ float As[16][128];
    __shared__ float Bs[16][64];

    float* gx = layer ? g_gx1 : g_gx0;
    int mBase = blockIdx.x * 128;
    int jBase = blockIdx.y * 64;
    int tid = threadIdx.x;
    int tmi = tid & 15;
    int tji = tid >> 4;

    float acc[8][4];
#pragma unroll
    for (int i = 0; i < 8; i++)
#pragma unroll
        for (int j = 0; j < 4; j++) acc[i][j] = 0.0f;

    for (int kk = 0; kk < 256; kk += 16) {
        __syncthreads();
#pragma unroll
        for (int i = 0; i < 2; i++) {
            int idx = tid + i * 256;
            int m   = idx & 127;
            int k4  = idx >> 7;
            int mg  = mBase + m;
            float msk;
            if (layer == 0) msk = (float)dxlz[mg];
            else            msk = (float)dx[((mg >> 8) << 9) + (mg & 255)];
            float4 v = *(const float4*)(x + (size_t)mg * 256 + kk + k4 * 4);
            As[k4 * 4 + 0][m] = v.x * msk;
            As[k4 * 4 + 1][m] = v.y * msk;
            As[k4 * 4 + 2][m] = v.z * msk;
            As[k4 * 4 + 3][m] = v.w * msk;
        }
        {
            int j  = tid & 63;
            int k4 = tid >> 6;
            float4 v = *(const float4*)(W + (size_t)(jBase + j) * 512 + kk + k4 * 4);
            Bs[k4 * 4 + 0][j] = v.x;
            Bs[k4 * 4 + 1][j] = v.y;
            Bs[k4 * 4 + 2][j] = v.z;
            Bs[k4 * 4 + 3][j] = v.w;
        }
        __syncthreads();
#pragma unroll
        for (int k = 0; k < 16; k++) {
            float4 a0 = *(const float4*)&As[k][tmi * 8];
            float4 a1 = *(const float4*)&As[k][tmi * 8 + 4];
            float4 bv = *(const float4*)&Bs[k][tji * 4];
            float am[8] = {a0.x, a0.y, a0.z, a0.w, a1.x, a1.y, a1.z, a1.w};
            float bm[4] = {bv.x, bv.y, bv.z, bv.w};
#pragma unroll
            for (int i = 0; i < 8; i++)
#pragma unroll
                for (int j = 0; j < 4; j++) acc[i][j] += am[i] * bm[j];
        }
    }

    float4 bb = *(const float4*)(bias + jBase + tji * 4);
#pragma unroll
    for (int i = 0; i < 8; i++) {
        int m = mBase + tmi * 8 + i;
        float4 o;
        o.x = acc[i][0] + bb.x;
        o.y = acc[i][1] + bb.y;
        o.z = acc[i][2] + bb.z;
        o.w = acc[i][3] + bb.w;
        *(float4*)(gx + (size_t)m * G3 + jBase + tji * 4) = o;
    }
}

// ---------------------------------------------------------------------------
// Persistent recurrence kernel: 128 CTAs x 128 threads, all 512 phases in one
// launch. Weights (both layers, this CTA's 16-u tile) resident in smem.
//
// Dynamic smem layout (floats):
//   sW    [2][3][512][16]   = 49152   (k 0..255 = W_ih h-part, 256..511 = W_hh)
//   sBias [2][768]          = 1536
//   sH    [2buf][2mat][32k][32b] = 4096
//   total 54784 floats = 219136 bytes
// ---------------------------------------------------------------------------
#define SW_FLOATS   49152
#define SBIAS_OFF   49152
#define SH_OFF      50688
#define SMEM_BYTES  (54784 * 4)

__global__ __launch_bounds__(128, 1) void persistent_kernel(
    const float* __restrict__ Wih0, const float* __restrict__ Whh0,
    const float* __restrict__ bhh0,
    const float* __restrict__ Wih1, const float* __restrict__ Whh1,
    const float* __restrict__ bhh1,
    const int* __restrict__ dx, const int* __restrict__ dxlz,
    float* __restrict__ out)
{
    extern __shared__ float sm[];
    float* sW    = sm;
    float* sBias = sm + SBIAS_OFF;
    float* sH    = sm + SH_OFF;

    int tid   = threadIdx.x;
    int uTile = (blockIdx.x >> 3) * 16;
    int bTile = (blockIdx.x & 7) * 32;
    int tb = tid & 15;    // 16 b-threads (x2 rows)
    int tu = tid >> 4;    // 8 u-threads (x2 cols)

    // ---- one-time: stage resident weights + biases ----
    for (int i = tid; i < 2 * 3 * 16 * 128; i += 128) {
        int l  = i / (3 * 16 * 128);
        int r  = i - l * (3 * 16 * 128);
        int g  = r / (16 * 128);
        int r2 = r - g * (16 * 128);
        int ul = r2 >> 7;          // 0..15
        int k  = (r2 & 127) * 4;   // 0..508
        int row = g * 256 + uTile + ul;
        const float* Wih = l ? Wih1 : Wih0;
        const float* Whh = l ? Whh1 : Whh0;
        float4 v;
        if (k < 256) v = *(const float4*)(Wih + (size_t)row * 512 + 256 + k);
        else         v = *(const float4*)(Whh + (size_t)row * 256 + (k - 256));
        float* d = sW + ((l * 3 + g) * 512 + k) * 16 + ul;
        d[0] = v.x; d[16] = v.y; d[32] = v.z; d[48] = v.w;
    }
    for (int i = tid; i < 1536; i += 128)
        sBias[i] = (i < 768) ? bhh0[i] : bhh1[i - 768];
    __syncthreads();

    // precompute staging indices (2 float4 per thread per chunk per matrix)
    int bb0 = tid & 31,        k40 = tid >> 5;          // 0..3
    int bb1 = (tid + 128) & 31, k41 = (tid + 128) >> 5; // 4..7

    unsigned phase = 0;
    for (int t = 0; t < TLEN; t++) {
        int p = t & 1, pn = p ^ 1;
        for (int l = 0; l < 2; l++) {
            const float* hA   = l ? g_h0[pn] : g_h1[p];
            const float* hB   = l ? g_h1[p]  : g_h0[p];
            float*       hOut = l ? g_h1[pn] : g_h0[pn];
            const float* gx   = l ? g_gx1    : g_gx0;
            const float* wl   = sW + l * (3 * 512 * 16);

            float accI[2][2][3], accH[2][2][3];
#pragma unroll
            for (int a = 0; a < 2; a++)
#pragma unroll
                for (int b = 0; b < 2; b++)
#pragma unroll
                    for (int g = 0; g < 3; g++) { accI[a][b][g] = 0.0f; accH[a][b][g] = 0.0f; }

            const float* pA0 = hA + (size_t)(bTile + bb0) * HID + k40 * 4;
            const float* pB0 = hB + (size_t)(bTile + bb0) * HID + k40 * 4;
            const float* pA1 = hA + (size_t)(bTile + bb1) * HID + k41 * 4;
            const float* pB1 = hB + (size_t)(bTile + bb1) * HID + k41 * 4;

            float4 ra0, ra1, rb0, rb1;
            // load + store chunk 0 into buf 0
            ra0 = __ldcg((const float4*)pA0);
            rb0 = __ldcg((const float4*)pB0);
            ra1 = __ldcg((const float4*)pA1);
            rb1 = __ldcg((const float4*)pB1);
            {
                float* dA0 = sH + k40 * 128 + bb0;
                float* dB0 = sH + 1024 + k40 * 128 + bb0;
                float* dA1 = sH + k41 * 128 + bb1;
                float* dB1 = sH + 1024 + k41 * 128 + bb1;
                dA0[0]=ra0.x; dA0[32]=ra0.y; dA0[64]=ra0.z; dA0[96]=ra0.w;
                dB0[0]=rb0.x; dB0[32]=rb0.y; dB0[64]=rb0.z; dB0[96]=rb0.w;
                dA1[0]=ra1.x; dA1[32]=ra1.y; dA1[64]=ra1.z; dA1[96]=ra1.w;
                dB1[0]=rb1.x; dB1[32]=rb1.y; dB1[64]=rb1.z; dB1[96]=rb1.w;
            }
            __syncthreads();

#pragma unroll 1
            for (int c = 0; c < 8; c++) {
                int buf = c & 1;
                if (c < 7) {
                    int off = (c + 1) * 32;
                    ra0 = __ldcg((const float4*)(pA0 + off));
                    rb0 = __ldcg((const float4*)(pB0 + off));
                    ra1 = __ldcg((const float4*)(pA1 + off));
                    rb1 = __ldcg((const float4*)(pB1 + off));
                }
                const float* sa = sH + buf * 2048;
                const float* sb = sa + 1024;
                const float* w0 = wl + (0 * 512 + c * 32) * 16;
                const float* w1 = wl + (1 * 512 + c * 32) * 16;
                const float* w2 = wl + (2 * 512 + c * 32) * 16;
#pragma unroll
                for (int k = 0; k < 32; k++) {
                    float2 a  = *(const float2*)(sa + k * 32 + tb * 2);
                    float2 hb = *(const float2*)(sb + k * 32 + tb * 2);
                    float2 wi, wh;
                    // gate 0
                    wi = *(const float2*)(w0 + k * 16 + tu * 2);
                    wh = *(const float2*)(w0 + 4096 + k * 16 + tu * 2);
                    accI[0][0][0] += a.x * wi.x; accI[0][1][0] += a.x * wi.y;
                    accI[1][0][0] += a.y * wi.x; accI[1][1][0] += a.y * wi.y;
                    accH[0][0][0] += hb.x * wh.x; accH[0][1][0] += hb.x * wh.y;
                    accH[1][0][0] += hb.y * wh.x; accH[1][1][0] += hb.y * wh.y;
                    // gate 1
                    wi = *(const float2*)(w1 + k * 16 + tu * 2);
                    wh = *(const float2*)(w1 + 4096 + k * 16 + tu * 2);
                    accI[0][0][1] += a.x * wi.x; accI[0][1][1] += a.x * wi.y;
                    accI[1][0][1] += a.y * wi.x; accI[1][1][1] += a.y * wi.y;
                    accH[0][0][1] += hb.x * wh.x; accH[0][1][1] += hb.x * wh.y;
                    accH[1][0][1] += hb.y * wh.x; accH[1][1][1] += hb.y * wh.y;
                    // gate 2
                    wi = *(const float2*)(w2 + k * 16 + tu * 2);
                    wh = *(const float2*)(w2 + 4096 + k * 16 + tu * 2);
                    accI[0][0][2] += a.x * wi.x; accI[0][1][2] += a.x * wi.y;
                    accI[1][0][2] += a.y * wi.x; accI[1][1][2] += a.y * wi.y;
                    accH[0][0][2] += hb.x * wh.x; accH[0][1][2] += hb.x * wh.y;
                    accH[1][0][2] += hb.y * wh.x; accH[1][1][2] += hb.y * wh.y;
                }
                if (c < 7) {
                    float* base = sH + (buf ^ 1) * 2048;
                    float* dA0 = base + k40 * 128 + bb0;
                    float* dB0 = base + 1024 + k40 * 128 + bb0;
                    float* dA1 = base + k41 * 128 + bb1;
                    float* dB1 = base + 1024 + k41 * 128 + bb1;
                    dA0[0]=ra0.x; dA0[32]=ra0.y; dA0[64]=ra0.z; dA0[96]=ra0.w;
                    dB0[0]=rb0.x; dB0[32]=rb0.y; dB0[64]=rb0.z; dB0[96]=rb0.w;
                    dA1[0]=ra1.x; dA1[32]=ra1.y; dA1[64]=ra1.z; dA1[96]=ra1.w;
                    dB1[0]=rb1.x; dB1[32]=rb1.y; dB1[64]=rb1.z; dB1[96]=rb1.w;
                }
                __syncthreads();
            }

            // ---- epilogue: masks, gates, bypass, writes ----
#pragma unroll
            for (int bi = 0; bi < 2; bi++) {
                int b = bTile + tb * 2 + bi;
                float mA, fB; int byp;
                if (l == 0) {
                    int b0  = dxlz[b * TLEN + t];
                    int dd0 = (t > 0) ? dx[(b * 2) * TLEN + t - 1] : 0;
                    mA = (float)dd0; fB = 1.0f - (float)dd0; byp = (b0 + dd0 == 0);
                } else {
                    int b1  = dx[(b * 2) * TLEN + t];
                    int dd1 = (t > 0) ? dx[(b * 2 + 1) * TLEN + t - 1] : 0;
                    mA = (float)b1; fB = 1.0f - (float)dd1; byp = (b1 + dd1 == 0);
                }
                const float* gxr = gx + (size_t)(b * TLEN + t) * G3;
                const float* bs  = sBias + l * 768;
#pragma unroll
                for (int ui = 0; ui < 2; ui++) {
                    int u = uTile + tu * 2 + ui;
                    float hprev = __ldcg(&hB[b * HID + u]);
                    float hUsed = hprev * fB;
                    float giR = __ldcg(&gxr[u])       + mA * accI[bi][ui][0];
                    float giZ = __ldcg(&gxr[256 + u]) + mA * accI[bi][ui][1];
                    float giN = __ldcg(&gxr[512 + u]) + mA * accI[bi][ui][2];
                    float ghR = bs[u]        + fB * accH[bi][ui][0];
                    float ghZ = bs[256 + u]  + fB * accH[bi][ui][1];
                    float ghN = bs[512 + u]  + fB * accH[bi][ui][2];
                    float r = 1.0f / (1.0f + expf(-(giR + ghR)));
                    float z = 1.0f / (1.0f + expf(-(giZ + ghZ)));
                    float n = tanhf(giN + r * ghN);
                    float hnew = (1.0f - z) * n + z * hUsed;
                    float res = byp ? hUsed : hnew;
                    __stcg(&hOut[b * HID + u], res);
                    out[(((size_t)l * BATCH + b) * TLEN + t) * HID + u] = res;
                }
            }

            // ---- grid barrier ----
            phase++;
            __threadfence();
            __syncthreads();
            if (tid == 0) {
                unsigned v = atomicAdd(&g_arrive, 1u) + 1u;
                if (v == (unsigned)NCTA * phase) {
                    g_release = phase;
                } else {
                    while (g_release < phase) __nanosleep(32);
                }
            }
            __syncthreads();
        }
    }
}

// ---------------------------------------------------------------------------
extern "C" void kernel_launch(void* const* d_in, const int* in_sizes, int n_in,
                              void* d_out, int out_size) {
    const float* x0    = (const float*)d_in[0];
    const float* x1    = (const float*)d_in[1];
    const float* hx0   = (const float*)d_in[2];
    const float* hx1   = (const float*)d_in[3];
    const float* W_ih0 = (const float*)d_in[4];
    const float* W_hh0 = (const float*)d_in[5];
    const float* b_ih0 = (const float*)d_in[6];
    const float* b_hh0 = (const float*)d_in[7];
    const float* W_ih1 = (const float*)d_in[8];
    const float* W_hh1 = (const float*)d_in[9];
    const float* b_ih1 = (const float*)d_in[10];
    const float* b_hh1 = (const float*)d_in[11];
    const int*   dx    = (const int*)d_in[12];
    const int*   dxlz  = (const int*)d_in[13];
    float* out = (float*)d_out;

    cudaFuncSetAttribute(persistent_kernel,
                         cudaFuncAttributeMaxDynamicSharedMemorySize, SMEM_BYTES);

    init_state<<<256, 256>>>(hx0, hx1);

    dim3 pgrid(512, 12);
    precompute_kernel<<<pgrid, 256>>>(x0, W_ih0, b_ih0, dx, dxlz, 0);
    precompute_kernel<<<pgrid, 256>>>(x1, W_ih1, b_ih1, dx, dxlz, 1);

    persistent_kernel<<<NCTA, 128, SMEM_BYTES>>>(
        W_ih0, W_hh0, b_hh0, W_ih1, W_hh1, b_hh1, dx, dxlz, out);
}

// round 10
// speedup vs baseline: 1.4032x; 1.0739x over previous
#include <cuda_runtime.h>
#include <math.h>

#define BATCH 256
#define TLEN  256
#define HID   256
#define G3    768   // 3*H
#define NCTA  128
#define NTHR  256

// Scratch (device globals — no allocation)
__device__ float g_gx0[BATCH * TLEN * G3];   // layer0 precomputed gi x-part (+b_ih)
__device__ float g_gx1[BATCH * TLEN * G3];   // layer1
__device__ float g_h0[2][BATCH * HID];       // double-buffered hidden state, parity = t&1
__device__ float g_h1[2][BATCH * HID];
__device__ unsigned g_arrive;
__device__ volatile unsigned g_release;

// ---------------------------------------------------------------------------
// init: copy initial hidden states into both parity buffers, reset barrier
// ---------------------------------------------------------------------------
__global__ void init_state(const float* __restrict__ hx0, const float* __restrict__ hx1) {
    int i = blockIdx.x * blockDim.x + threadIdx.x;
    if (i == 0) { g_arrive = 0u; g_release = 0u; }
    if (i < BATCH * HID) {
        g_h0[0][i] = hx0[i];
        g_h0[1][i] = hx0[i];
        g_h1[0][i] = hx1[i];
        g_h1[1][i] = hx1[i];
    }
}

// ---------------------------------------------------------------------------
// Precompute: gx[m][j] = mask[m] * sum_k x[m][k]*W[j][k] + b_ih[j]   (unchanged)
// ---------------------------------------------------------------------------
__global__ __launch_bounds__(256) void precompute_kernel(
    const float* __restrict__ x, const float* __restrict__ W,
    const float* __restrict__ bias,
    const int* __restrict__ dx, const int* __restrict__ dxlz, int layer)
{
    __shared__ float As[16][128];
    __shared__ float Bs[16][64];

    float* gx = layer ? g_gx1 : g_gx0;
    int mBase = blockIdx.x * 128;
    int jBase = blockIdx.y * 64;
    int tid = threadIdx.x;
    int tmi = tid & 15;
    int tji = tid >> 4;

    float acc[8][4];
#pragma unroll
    for (int i = 0; i < 8; i++)
#pragma unroll
        for (int j = 0; j < 4; j++) acc[i][j] = 0.0f;

    for (int kk = 0; kk < 256; kk += 16) {
        __syncthreads();
#pragma unroll
        for (int i = 0; i < 2; i++) {
            int idx = tid + i * 256;
            int m   = idx & 127;
            int k4  = idx >> 7;
            int mg  = mBase + m;
            float msk;
            if (layer == 0) msk = (float)dxlz[mg];
            else            msk = (float)dx[((mg >> 8) << 9) + (mg & 255)];
            float4 v = *(const float4*)(x + (size_t)mg * 256 + kk + k4 * 4);
            As[k4 * 4 + 0][m] = v.x * msk;
            As[k4 * 4 + 1][m] = v.y * msk;
            As[k4 * 4 + 2][m] = v.z * msk;
            As[k4 * 4 + 3][m] = v.w * msk;
        }
        {
            int j  = tid & 63;
            int k4 = tid >> 6;
            float4 v = *(const float4*)(W + (size_t)(jBase + j) * 512 + kk + k4 * 4);
            Bs[k4 * 4 + 0][j] = v.x;
            Bs[k4 * 4 + 1][j] = v.y;
            Bs[k4 * 4 + 2][j] = v.z;
            Bs[k4 * 4 + 3][j] = v.w;
        }
        __syncthreads();
#pragma unroll
        for (int k = 0; k < 16; k++) {
            float4 a0 = *(const float4*)&As[k][tmi * 8];
            float4 a1 = *(const float4*)&As[k][tmi * 8 + 4];
            float4 bv = *(const float4*)&Bs[k][tji * 4];
            float am[8] = {a0.x, a0.y, a0.z, a0.w, a1.x, a1.y, a1.z, a1.w};
            float bm[4] = {bv.x, bv.y, bv.z, bv.w};
#pragma unroll
            for (int i = 0; i < 8; i++)
#pragma unroll
                for (int j = 0; j < 4; j++) acc[i][j] += am[i] * bm[j];
        }
    }

    float4 bb = *(const float4*)(bias + jBase + tji * 4);
#pragma unroll
    for (int i = 0; i < 8; i++) {
        int m = mBase + tmi * 8 + i;
        float4 o;
        o.x = acc[i][0] + bb.x;
        o.y = acc[i][1] + bb.y;
        o.z = acc[i][2] + bb.z;
        o.w = acc[i][3] + bb.w;
        *(float4*)(gx + (size_t)m * G3 + jBase + tji * 4) = o;
    }
}

// ---------------------------------------------------------------------------
// Persistent recurrence kernel: 128 CTAs x 256 threads (split-K), all 512
// phases in one launch. Weights (both layers, this CTA's 16-u tile) resident
// in smem, repacked as [l][k][u-pair(8)][12] where 12 =
//   {Wi g0 u0,u1, Wi g1 u0,u1, Wi g2 u0,u1, Wh g0 u0,u1, Wh g1 u0,u1, Wh g2 u0,u1}
// Dynamic smem: sW 49152 floats (192KB) + sH 4096 floats (16KB) = 212992 B.
//   sH layout: [half][mat][k32][b32]  (single buffer; regs double-buffer)
// ---------------------------------------------------------------------------
#define SW_SIZE    49152
#define SH_OFF     49152
#define SH_SIZE    4096
#define SMEM_BYTES ((SW_SIZE + SH_SIZE) * 4)

__global__ __launch_bounds__(NTHR, 1) void persistent_kernel(
    const float* __restrict__ Wih0, const float* __restrict__ Whh0,
    const float* __restrict__ bhh0,
    const float* __restrict__ Wih1, const float* __restrict__ Whh1,
    const float* __restrict__ bhh1,
    const int* __restrict__ dx, const int* __restrict__ dxlz,
    float* __restrict__ out)
{
    extern __shared__ float sm[];
    float* sW = sm;
    float* sH = sm + SH_OFF;

    int tid   = threadIdx.x;
    int uTile = (blockIdx.x >> 3) * 16;
    int bTile = (blockIdx.x & 7) * 32;
    int half  = tid >> 7;          // split-K half: k in [half*128, half*128+128)
    int t128  = tid & 127;
    int tb = t128 & 15;            // 16 b-threads (x2 rows)
    int tu = t128 >> 4;            // 8 u-threads (x2 cols)

    // ---- one-time: stage resident weights (repacked) ----
    for (int i = tid; i < SW_SIZE; i += NTHR) {
        int k  = i & 255;
        int r2 = i >> 12;          // 0..11
        int u  = (i >> 8) & 15;
        int g  = r2 % 3;
        int m  = (r2 / 3) & 1;
        int l  = r2 / 6;
        int row = g * 256 + uTile + u;
        float v;
        if (m == 0) {
            const float* W = l ? Wih1 : Wih0;
            v = W[(size_t)row * 512 + 256 + k];
        } else {
            const float* W = l ? Whh1 : Whh0;
            v = W[(size_t)row * 256 + k];
        }
        sW[((l * 256 + k) * 8 + (u >> 1)) * 12 + m * 6 + g * 2 + (u & 1)] = v;
    }

    // ---- biases in registers (epilogue threads only) ----
    float rb0g[3][2], rb1g[3][2];
    if (tid < 128) {
#pragma unroll
        for (int g = 0; g < 3; g++)
#pragma unroll
            for (int ui = 0; ui < 2; ui++) {
                int u = g * 256 + uTile + tu * 2 + ui;
                rb0g[g][ui] = bhh0[u];
                rb1g[g][ui] = bhh1[u];
            }
    }
    __syncthreads();

    // staging geometry: per thread 4 float4 per chunk (j=0..3)
    int b_s = t128 & 31;
    int k4base = (t128 >> 5);      // 0..3

    unsigned phase = 0;
    for (int t = 0; t < TLEN; t++) {
        int p = t & 1, pn = p ^ 1;
#pragma unroll 1
        for (int l = 0; l < 2; l++) {
            const float* hA   = l ? g_h0[pn] : g_h1[p];
            const float* hB   = l ? g_h1[p]  : g_h0[p];
            float*       hOut = l ? g_h1[pn] : g_h0[pn];
            const float* gx   = l ? g_gx1    : g_gx0;

            // ---- epilogue operand prefetch (hidden under GEMM) ----
            float pgx[2][3][2], phb[2][2], mAv[2], fBv[2];
            int byp[2];
            if (tid < 128) {
#pragma unroll
                for (int bi = 0; bi < 2; bi++) {
                    int b = bTile + tb * 2 + bi;
                    if (l == 0) {
                        int b0  = dxlz[b * TLEN + t];
                        int dd0 = (t > 0) ? dx[(b * 2) * TLEN + t - 1] : 0;
                        mAv[bi] = (float)dd0; fBv[bi] = 1.0f - (float)dd0;
                        byp[bi] = (b0 + dd0 == 0);
                    } else {
                        int b1  = dx[(b * 2) * TLEN + t];
                        int dd1 = (t > 0) ? dx[(b * 2 + 1) * TLEN + t - 1] : 0;
                        mAv[bi] = (float)b1; fBv[bi] = 1.0f - (float)dd1;
                        byp[bi] = (b1 + dd1 == 0);
                    }
                    const float* gxr = gx + (size_t)(b * TLEN + t) * G3;
                    int u = uTile + tu * 2;
                    float2 v0 = __ldcg((const float2*)(gxr + u));
                    float2 v1 = __ldcg((const float2*)(gxr + 256 + u));
                    float2 v2 = __ldcg((const float2*)(gxr + 512 + u));
                    pgx[bi][0][0] = v0.x; pgx[bi][0][1] = v0.y;
                    pgx[bi][1][0] = v1.x; pgx[bi][1][1] = v1.y;
                    pgx[bi][2][0] = v2.x; pgx[bi][2][1] = v2.y;
                    float2 hv = __ldcg((const float2*)(hB + (size_t)b * HID + u));
                    phb[bi][0] = hv.x; phb[bi][1] = hv.y;
                }
            }

            float acc[24];
#pragma unroll
            for (int j = 0; j < 24; j++) acc[j] = 0.0f;

            int kBase = half * 128;
            float4 rg[4];
            // load chunk 0 into regs
#pragma unroll
            for (int j = 0; j < 4; j++) {
                const float* src = (j >> 1) ? hB : hA;
                int k4 = k4base + 4 * (j & 1);
                rg[j] = __ldcg((const float4*)(src + (size_t)(bTile + b_s) * HID + kBase + k4 * 4));
            }
            // store chunk 0 to smem
#pragma unroll
            for (int j = 0; j < 4; j++) {
                int k4 = k4base + 4 * (j & 1);
                float* d = sH + half * 2048 + (j >> 1) * 1024 + (k4 * 4) * 32 + b_s;
                d[0] = rg[j].x; d[32] = rg[j].y; d[64] = rg[j].z; d[96] = rg[j].w;
            }
            __syncthreads();

#pragma unroll 1
            for (int c = 0; c < 4; c++) {
                if (c < 3) {
                    int koff = kBase + (c + 1) * 32;
#pragma unroll
                    for (int j = 0; j < 4; j++) {
                        const float* src = (j >> 1) ? hB : hA;
                        int k4 = k4base + 4 * (j & 1);
                        rg[j] = __ldcg((const float4*)(src + (size_t)(bTile + b_s) * HID + koff + k4 * 4));
                    }
                }
                const float* sa = sH + half * 2048;
                const float* sb = sa + 1024;
                const float* wbase = sW + ((size_t)(l * 256 + kBase + c * 32) * 8 + tu) * 12;
#pragma unroll
                for (int k = 0; k < 32; k++) {
                    float2 a  = *(const float2*)(sa + k * 32 + tb * 2);
                    float2 hb = *(const float2*)(sb + k * 32 + tb * 2);
                    const float* w = wbase + k * 96;
                    float4 wA = *(const float4*)(w);
                    float4 wB = *(const float4*)(w + 4);
                    float4 wC = *(const float4*)(w + 8);
                    acc[0]  += a.x * wA.x;  acc[3]  += a.x * wA.y;
                    acc[6]  += a.y * wA.x;  acc[9]  += a.y * wA.y;
                    acc[1]  += a.x * wA.z;  acc[4]  += a.x * wA.w;
                    acc[7]  += a.y * wA.z;  acc[10] += a.y * wA.w;
                    acc[2]  += a.x * wB.x;  acc[5]  += a.x * wB.y;
                    acc[8]  += a.y * wB.x;  acc[11] += a.y * wB.y;
                    acc[12] += hb.x * wB.z; acc[15] += hb.x * wB.w;
                    acc[18] += hb.y * wB.z; acc[21] += hb.y * wB.w;
                    acc[13] += hb.x * wC.x; acc[16] += hb.x * wC.y;
                    acc[19] += hb.y * wC.x; acc[22] += hb.y * wC.y;
                    acc[14] += hb.x * wC.z; acc[17] += hb.x * wC.w;
                    acc[20] += hb.y * wC.z; acc[23] += hb.y * wC.w;
                }
                __syncthreads();
                if (c < 3) {
#pragma unroll
                    for (int j = 0; j < 4; j++) {
                        int k4 = k4base + 4 * (j & 1);
                        float* d = sH + half * 2048 + (j >> 1) * 1024 + (k4 * 4) * 32 + b_s;
                        d[0] = rg[j].x; d[32] = rg[j].y; d[64] = rg[j].z; d[96] = rg[j].w;
                    }
                    __syncthreads();
                }
            }

            // ---- split-K reduction ----
            float* sRed = sH;
            if (tid >= 128) {
#pragma unroll
                for (int j = 0; j < 24; j++) sRed[t128 * 24 + j] = acc[j];
            }
            __syncthreads();

            if (tid < 128) {
#pragma unroll
                for (int j = 0; j < 24; j++) acc[j] += sRed[tid * 24 + j];

                // ---- epilogue: gates, bypass, writes ----
#pragma unroll
                for (int bi = 0; bi < 2; bi++) {
                    int b = bTile + tb * 2 + bi;
                    float res2[2];
#pragma unroll
                    for (int ui = 0; ui < 2; ui++) {
                        int ai = (bi * 2 + ui) * 3;
                        float hUsed = phb[bi][ui] * fBv[bi];
                        float giR = pgx[bi][0][ui] + mAv[bi] * acc[ai + 0];
                        float giZ = pgx[bi][1][ui] + mAv[bi] * acc[ai + 1];
                        float giN = pgx[bi][2][ui] + mAv[bi] * acc[ai + 2];
                        float bR = l ? rb1g[0][ui] : rb0g[0][ui];
                        float bZ = l ? rb1g[1][ui] : rb0g[1][ui];
                        float bN = l ? rb1g[2][ui] : rb0g[2][ui];
                        float ghR = bR + fBv[bi] * acc[12 + ai + 0];
                        float ghZ = bZ + fBv[bi] * acc[12 + ai + 1];
                        float ghN = bN + fBv[bi] * acc[12 + ai + 2];
                        float r = 1.0f / (1.0f + expf(-(giR + ghR)));
                        float z = 1.0f / (1.0f + expf(-(giZ + ghZ)));
                        float n = tanhf(giN + r * ghN);
                        float hnew = (1.0f - z) * n + z * hUsed;
                        res2[ui] = byp[bi] ? hUsed : hnew;
                    }
                    int u = uTile + tu * 2;
                    float2 rv; rv.x = res2[0]; rv.y = res2[1];
                    __stcg((float2*)(hOut + (size_t)b * HID + u), rv);
                    __stcg((float2*)(out + (((size_t)l * BATCH + b) * TLEN + t) * HID + u), rv);
                }
            }

            // ---- grid barrier (known-good form) ----
            phase++;
            __threadfence();
            __syncthreads();
            if (tid == 0) {
                unsigned v = atomicAdd(&g_arrive, 1u) + 1u;
                if (v == (unsigned)NCTA * phase) {
                    g_release = phase;
                } else {
                    while (g_release < phase) __nanosleep(32);
                }
            }
            __syncthreads();
        }
    }
}

// ---------------------------------------------------------------------------
extern "C" void kernel_launch(void* const* d_in, const int* in_sizes, int n_in,
                              void* d_out, int out_size) {
    const float* x0    = (const float*)d_in[0];
    const float* x1    = (const float*)d_in[1];
    const float* hx0   = (const float*)d_in[2];
    const float* hx1   = (const float*)d_in[3];
    const float* W_ih0 = (const float*)d_in[4];
    const float* W_hh0 = (const float*)d_in[5];
    const float* b_ih0 = (const float*)d_in[6];
    const float* b_hh0 = (const float*)d_in[7];
    const float* W_ih1 = (const float*)d_in[8];
    const float* W_hh1 = (const float*)d_in[9];
    const float* b_ih1 = (const float*)d_in[10];
    const float* b_hh1 = (const float*)d_in[11];
    const int*   dx    = (const int*)d_in[12];
    const int*   dxlz  = (const int*)d_in[13];
    float* out = (float*)d_out;

    cudaFuncSetAttribute(persistent_kernel,
                         cudaFuncAttributeMaxDynamicSharedMemorySize, SMEM_BYTES);

    init_state<<<256, 256>>>(hx0, hx1);

    dim3 pgrid(512, 12);
    precompute_kernel<<<pgrid, 256>>>(x0, W_ih0, b_ih0, dx, dxlz, 0);
    precompute_kernel<<<pgrid, 256>>>(x1, W_ih1, b_ih1, dx, dxlz, 1);

    persistent_kernel<<<NCTA, NTHR, SMEM_BYTES>>>(
        W_ih0, W_hh0, b_hh0, W_ih1, W_hh1, b_hh1, dx, dxlz, out);
}

// round 11
// speedup vs baseline: 1.5200x; 1.0832x over previous
#include <cuda_runtime.h>
#include <math.h>

#define BATCH 256
#define TLEN  256
#define HID   256
#define G3    768   // 3*H
#define NCTA  128
#define NTHR  256
#define NPHASE 512

// Scratch (device globals — no allocation)
__device__ float g_gx0[BATCH * TLEN * G3];   // layer0 precomputed gi x-part (+b_ih)
__device__ float g_gx1[BATCH * TLEN * G3];   // layer1
__device__ float g_h0[2][BATCH * HID];       // double-buffered hidden state, parity = t&1
__device__ float g_h1[2][BATCH * HID];
__device__ unsigned g_arrive;
__device__ volatile unsigned g_release;

// ---------------------------------------------------------------------------
__global__ void init_state(const float* __restrict__ hx0, const float* __restrict__ hx1) {
    int i = blockIdx.x * blockDim.x + threadIdx.x;
    if (i == 0) { g_arrive = 0u; g_release = 0u; }
    if (i < BATCH * HID) {
        g_h0[0][i] = hx0[i];
        g_h0[1][i] = hx0[i];
        g_h1[0][i] = hx1[i];
        g_h1[1][i] = hx1[i];
    }
}

// ---------------------------------------------------------------------------
// Precompute: gx[m][j] = mask[m] * sum_k x[m][k]*W[j][k] + b_ih[j]   (unchanged)
// ---------------------------------------------------------------------------
__global__ __launch_bounds__(256) void precompute_kernel(
    const float* __restrict__ x, const float* __restrict__ W,
    const float* __restrict__ bias,
    const int* __restrict__ dx, const int* __restrict__ dxlz, int layer)
{
    __shared__ float As[16][128];
    __shared__ float Bs[16][64];

    float* gx = layer ? g_gx1 : g_gx0;
    int mBase = blockIdx.x * 128;
    int jBase = blockIdx.y * 64;
    int tid = threadIdx.x;
    int tmi = tid & 15;
    int tji = tid >> 4;

    float acc[8][4];
#pragma unroll
    for (int i = 0; i < 8; i++)
#pragma unroll
        for (int j = 0; j < 4; j++) acc[i][j] = 0.0f;

    for (int kk = 0; kk < 256; kk += 16) {
        __syncthreads();
#pragma unroll
        for (int i = 0; i < 2; i++) {
            int idx = tid + i * 256;
            int m   = idx & 127;
            int k4  = idx >> 7;
            int mg  = mBase + m;
            float msk;
            if (layer == 0) msk = (float)dxlz[mg];
            else            msk = (float)dx[((mg >> 8) << 9) + (mg & 255)];
            float4 v = *(const float4*)(x + (size_t)mg * 256 + kk + k4 * 4);
            As[k4 * 4 + 0][m] = v.x * msk;
            As[k4 * 4 + 1][m] = v.y * msk;
            As[k4 * 4 + 2][m] = v.z * msk;
            As[k4 * 4 + 3][m] = v.w * msk;
        }
        {
            int j  = tid & 63;
            int k4 = tid >> 6;
            float4 v = *(const float4*)(W + (size_t)(jBase + j) * 512 + kk + k4 * 4);
            Bs[k4 * 4 + 0][j] = v.x;
            Bs[k4 * 4 + 1][j] = v.y;
            Bs[k4 * 4 + 2][j] = v.z;
            Bs[k4 * 4 + 3][j] = v.w;
        }
        __syncthreads();
#pragma unroll
        for (int k = 0; k < 16; k++) {
            float4 a0 = *(const float4*)&As[k][tmi * 8];
            float4 a1 = *(const float4*)&As[k][tmi * 8 + 4];
            float4 bv = *(const float4*)&Bs[k][tji * 4];
            float am[8] = {a0.x, a0.y, a0.z, a0.w, a1.x, a1.y, a1.z, a1.w};
            float bm[4] = {bv.x, bv.y, bv.z, bv.w};
#pragma unroll
            for (int i = 0; i < 8; i++)
#pragma unroll
                for (int j = 0; j < 4; j++) acc[i][j] += am[i] * bm[j];
        }
    }

    float4 bb = *(const float4*)(bias + jBase + tji * 4);
#pragma unroll
    for (int i = 0; i < 8; i++) {
        int m = mBase + tmi * 8 + i;
        float4 o;
        o.x = acc[i][0] + bb.x;
        o.y = acc[i][1] + bb.y;
        o.z = acc[i][2] + bb.z;
        o.w = acc[i][3] + bb.w;
        *(float4*)(gx + (size_t)m * G3 + jBase + tji * 4) = o;
    }
}

// ---------------------------------------------------------------------------
// Persistent recurrence kernel. 128 CTAs x 256 threads (split-K halves).
// smem: sW 49152 floats (192KB, resident weights, repacked) +
//       sH 2 x 4096 floats (double-buffered h stage / reduction) = 224KB.
// Critical-path ordering per phase:
//   [barrier release] -> load hA chunk0 (hB chunk0 was prefetched pre-barrier)
//   -> GEMM (reg-double-buffered chunks) -> split reduction (both halves)
//   -> epilogue (half outputs each) -> hOut stcg + fence + arrive
//   -> out stores + next-phase hB/epilogue prefetch -> wait release.
// ---------------------------------------------------------------------------
#define SW_SIZE    49152
#define SH_OFF     49152
#define SMEM_BYTES ((SW_SIZE + 8192) * 4)

__device__ __forceinline__ void phase_ptrs(int ph, const float*& hA, const float*& hB,
                                           float*& hOut, const float*& gx) {
    int t = ph >> 1, l = ph & 1, p = t & 1, pn = p ^ 1;
    if (l == 0) { hA = g_h1[p];  hB = g_h0[p]; hOut = g_h0[pn]; gx = g_gx0; }
    else        { hA = g_h0[pn]; hB = g_h1[p]; hOut = g_h1[pn]; gx = g_gx1; }
}

__global__ __launch_bounds__(NTHR, 1) void persistent_kernel(
    const float* __restrict__ Wih0, const float* __restrict__ Whh0,
    const float* __restrict__ bhh0,
    const float* __restrict__ Wih1, const float* __restrict__ Whh1,
    const float* __restrict__ bhh1,
    const int* __restrict__ dx, const int* __restrict__ dxlz,
    float* __restrict__ out)
{
    extern __shared__ float sm[];
    float* sW = sm;
    float* sH = sm + SH_OFF;     // two 4096-float buffers

    int tid   = threadIdx.x;
    int uTile = (blockIdx.x >> 3) * 16;
    int bTile = (blockIdx.x & 7) * 32;
    int half  = tid >> 7;          // split-K half: k in [half*128, half*128+128)
    int t128  = tid & 127;
    int tb = t128 & 15;            // 16 b-threads
    int tu = t128 >> 4;            // 8 u-threads (x2 cols)
    int kBase = half * 128;

    // ---- one-time: stage resident weights (repacked [l][k][u-pair(8)][12]) ----
    for (int i = tid; i < SW_SIZE; i += NTHR) {
        int k  = i & 255;
        int r2 = i >> 12;          // 0..11
        int u  = (i >> 8) & 15;
        int g  = r2 % 3;
        int m  = (r2 / 3) & 1;
        int l  = r2 / 6;
        int row = g * 256 + uTile + u;
        float v;
        if (m == 0) {
            const float* W = l ? Wih1 : Wih0;
            v = W[(size_t)row * 512 + 256 + k];
        } else {
            const float* W = l ? Whh1 : Whh0;
            v = W[(size_t)row * 256 + k];
        }
        sW[((l * 256 + k) * 8 + (u >> 1)) * 12 + m * 6 + g * 2 + (u & 1)] = v;
    }

    // ---- biases in registers (all threads; epilogue is split across halves) ----
    float rb0g[3][2], rb1g[3][2];
#pragma unroll
    for (int g = 0; g < 3; g++)
#pragma unroll
        for (int ui = 0; ui < 2; ui++) {
            int u = g * 256 + uTile + tu * 2 + ui;
            rb0g[g][ui] = bhh0[u];
            rb1g[g][ui] = bhh1[u];
        }
    __syncthreads();

    // staging geometry
    int b_s = t128 & 31;
    int k4base = (t128 >> 5);      // 0..3
    const size_t hOffA = (size_t)(bTile + b_s) * HID + kBase + k4base * 4;
    const size_t hOffB = (size_t)(bTile + b_s) * HID + kBase + (k4base + 4) * 4;
    int bMine = bTile + tb * 2 + half;   // this thread's epilogue batch row
    int uMine = uTile + tu * 2;
    int keepBase = half * 6;             // acc base for this thread's bi(=half)
    int sendBase = 6 - keepBase;         // acc base shipped to the other half

    // ---- prologue: prefetch phase 0 operands ----
    float4 rnb0, rnb1;                    // next-phase hB chunk0
    float pgx[3][2], phb[2], mAv, fBv;
    int byp;
    {
        const float *hA, *hB, *gx; float* hOut;
        phase_ptrs(0, hA, hB, hOut, gx);
        rnb0 = __ldcg((const float4*)(hB + hOffA));
        rnb1 = __ldcg((const float4*)(hB + hOffB));
        int b0  = dxlz[bMine * TLEN + 0];
        mAv = 0.0f; fBv = 1.0f; byp = (b0 == 0);
        const float* gxr = gx + (size_t)(bMine * TLEN + 0) * G3;
        float2 v0 = __ldcg((const float2*)(gxr + uMine));
        float2 v1 = __ldcg((const float2*)(gxr + 256 + uMine));
        float2 v2 = __ldcg((const float2*)(gxr + 512 + uMine));
        pgx[0][0] = v0.x; pgx[0][1] = v0.y;
        pgx[1][0] = v1.x; pgx[1][1] = v1.y;
        pgx[2][0] = v2.x; pgx[2][1] = v2.y;
        float2 hv = __ldcg((const float2*)(hB + (size_t)bMine * HID + uMine));
        phb[0] = hv.x; phb[1] = hv.y;
    }

#pragma unroll 1
    for (int ph = 0; ph < NPHASE; ph++) {
        int t = ph >> 1, l = ph & 1;
        const float *hA, *hB, *gx; float* hOut;
        phase_ptrs(ph, hA, hB, hOut, gx);

        // ---- post-barrier: load fresh hA chunk0, stage chunk0 to buf0 ----
        float4 ra0 = __ldcg((const float4*)(hA + hOffA));
        float4 ra1 = __ldcg((const float4*)(hA + hOffB));
        {
            float* base = sH + half * 2048;
            float* dA0 = base + (k4base * 4) * 32 + b_s;
            float* dA1 = base + ((k4base + 4) * 4) * 32 + b_s;
            float* dB0 = dA0 + 1024;
            float* dB1 = dA1 + 1024;
            dA0[0]=ra0.x;  dA0[32]=ra0.y;  dA0[64]=ra0.z;  dA0[96]=ra0.w;
            dA1[0]=ra1.x;  dA1[32]=ra1.y;  dA1[64]=ra1.z;  dA1[96]=ra1.w;
            dB0[0]=rnb0.x; dB0[32]=rnb0.y; dB0[64]=rnb0.z; dB0[96]=rnb0.w;
            dB1[0]=rnb1.x; dB1[32]=rnb1.y; dB1[64]=rnb1.z; dB1[96]=rnb1.w;
        }
        __syncthreads();

        float acc[24];
#pragma unroll
        for (int j = 0; j < 24; j++) acc[j] = 0.0f;

        float4 rg[4];
#pragma unroll 1
        for (int c = 0; c < 4; c++) {
            if (c < 3) {
                int koff = (c + 1) * 32;
                rg[0] = __ldcg((const float4*)(hA + hOffA + koff));
                rg[1] = __ldcg((const float4*)(hA + hOffB + koff));
                rg[2] = __ldcg((const float4*)(hB + hOffA + koff));
                rg[3] = __ldcg((const float4*)(hB + hOffB + koff));
            }
            const float* sa = sH + (c & 1) * 4096 + half * 2048;
            const float* sb = sa + 1024;
            const float* wbase = sW + ((size_t)(l * 256 + kBase + c * 32) * 8 + tu) * 12;
#pragma unroll
            for (int k = 0; k < 32; k++) {
                float2 a  = *(const float2*)(sa + k * 32 + tb * 2);
                float2 hb = *(const float2*)(sb + k * 32 + tb * 2);
                const float* w = wbase + k * 96;
                float4 wA = *(const float4*)(w);
                float4 wB = *(const float4*)(w + 4);
                float4 wC = *(const float4*)(w + 8);
                acc[0]  += a.x * wA.x;  acc[3]  += a.x * wA.y;
                acc[6]  += a.y * wA.x;  acc[9]  += a.y * wA.y;
                acc[1]  += a.x * wA.z;  acc[4]  += a.x * wA.w;
                acc[7]  += a.y * wA.z;  acc[10] += a.y * wA.w;
                acc[2]  += a.x * wB.x;  acc[5]  += a.x * wB.y;
                acc[8]  += a.y * wB.x;  acc[11] += a.y * wB.y;
                acc[12] += hb.x * wB.z; acc[15] += hb.x * wB.w;
                acc[18] += hb.y * wB.z; acc[21] += hb.y * wB.w;
                acc[13] += hb.x * wC.x; acc[16] += hb.x * wC.y;
                acc[19] += hb.y * wC.x; acc[22] += hb.y * wC.y;
                acc[14] += hb.x * wC.z; acc[17] += hb.x * wC.w;
                acc[20] += hb.y * wC.z; acc[23] += hb.y * wC.w;
            }
            if (c < 3) {
                float* base = sH + ((c + 1) & 1) * 4096 + half * 2048;
                float* dA0 = base + (k4base * 4) * 32 + b_s;
                float* dA1 = base + ((k4base + 4) * 4) * 32 + b_s;
                float* dB0 = dA0 + 1024;
                float* dB1 = dA1 + 1024;
                dA0[0]=rg[0].x; dA0[32]=rg[0].y; dA0[64]=rg[0].z; dA0[96]=rg[0].w;
                dA1[0]=rg[1].x; dA1[32]=rg[1].y; dA1[64]=rg[1].z; dA1[96]=rg[1].w;
                dB0[0]=rg[2].x; dB0[32]=rg[2].y; dB0[64]=rg[2].z; dB0[96]=rg[2].w;
                dB1[0]=rg[3].x; dB1[32]=rg[3].y; dB1[64]=rg[3].z; dB1[96]=rg[3].w;
                __syncthreads();
            }
        }

        // ---- split-K exchange: each half ships the other half's bi partials ----
        // (chunk-3 compute reads buf1; sRed lives in buf0 — disjoint, no sync needed)
        float* sRed = sH;                       // 2 x 1536 floats in buf0
        {
            float* wr = sRed + half * 1536 + t128 * 12;
#pragma unroll
            for (int j = 0; j < 6; j++) {
                wr[j]     = acc[sendBase + j];
                wr[6 + j] = acc[12 + sendBase + j];
            }
        }
        __syncthreads();
        {
            const float* rd = sRed + (half ^ 1) * 1536 + t128 * 12;
#pragma unroll
            for (int j = 0; j < 6; j++) {
                acc[keepBase + j]      += rd[j];
                acc[12 + keepBase + j] += rd[6 + j];
            }
        }

        // ---- epilogue: this thread's single batch row, 2 u outputs ----
        float res2[2];
#pragma unroll
        for (int ui = 0; ui < 2; ui++) {
            int ai = keepBase + ui * 3;
            float hUsed = phb[ui] * fBv;
            float giR = pgx[0][ui] + mAv * acc[ai + 0];
            float giZ = pgx[1][ui] + mAv * acc[ai + 1];
            float giN = pgx[2][ui] + mAv * acc[ai + 2];
            float bR = l ? rb1g[0][ui] : rb0g[0][ui];
            float bZ = l ? rb1g[1][ui] : rb0g[1][ui];
            float bN = l ? rb1g[2][ui] : rb0g[2][ui];
            float ghR = bR + fBv * acc[12 + ai + 0];
            float ghZ = bZ + fBv * acc[12 + ai + 1];
            float ghN = bN + fBv * acc[12 + ai + 2];
            float r = 1.0f / (1.0f + expf(-(giR + ghR)));
            float z = 1.0f / (1.0f + expf(-(giZ + ghZ)));
            float n = tanhf(giN + r * ghN);
            float hnew = (1.0f - z) * n + z * hUsed;
            res2[ui] = byp ? hUsed : hnew;
        }
        float2 rv; rv.x = res2[0]; rv.y = res2[1];
        __stcg((float2*)(hOut + (size_t)bMine * HID + uMine), rv);

        // ---- arrive ASAP; defer out-store + prefetch to the wait window ----
        __threadfence();
        __syncthreads();
        unsigned target = (unsigned)(ph + 1);
        if (tid == 0) {
            unsigned v = atomicAdd(&g_arrive, 1u) + 1u;
            if (v == (unsigned)NCTA * target) g_release = target;
        }

        __stcg((float2*)(out + (((size_t)l * BATCH + bMine) * TLEN + t) * HID + uMine), rv);

        if (ph + 1 < NPHASE) {
            int q = ph + 1, tq = q >> 1, lq = q & 1;
            const float *hAq, *hBq, *gxq; float* hOq;
            phase_ptrs(q, hAq, hBq, hOq, gxq);
            rnb0 = __ldcg((const float4*)(hBq + hOffA));
            rnb1 = __ldcg((const float4*)(hBq + hOffB));
            if (lq == 0) {
                int b0  = dxlz[bMine * TLEN + tq];
                int dd0 = dx[(bMine * 2) * TLEN + tq - 1];
                mAv = (float)dd0; fBv = 1.0f - (float)dd0; byp = (b0 + dd0 == 0);
            } else {
                int b1  = dx[(bMine * 2) * TLEN + tq];
                int dd1 = (tq > 0) ? dx[(bMine * 2 + 1) * TLEN + tq - 1] : 0;
                mAv = (float)b1; fBv = 1.0f - (float)dd1; byp = (b1 + dd1 == 0);
            }
            const float* gxr = gxq + (size_t)(bMine * TLEN + tq) * G3;
            float2 v0 = __ldcg((const float2*)(gxr + uMine));
            float2 v1 = __ldcg((const float2*)(gxr + 256 + uMine));
            float2 v2 = __ldcg((const float2*)(gxr + 512 + uMine));
            pgx[0][0] = v0.x; pgx[0][1] = v0.y;
            pgx[1][0] = v1.x; pgx[1][1] = v1.y;
            pgx[2][0] = v2.x; pgx[2][1] = v2.y;
            float2 hv = __ldcg((const float2*)(hBq + (size_t)bMine * HID + uMine));
            phb[0] = hv.x; phb[1] = hv.y;

            if (tid == 0) {
                while (g_release < target) __nanosleep(32);
            }
            __syncthreads();
        }
    }
}

// ---------------------------------------------------------------------------
extern "C" void kernel_launch(void* const* d_in, const int* in_sizes, int n_in,
                              void* d_out, int out_size) {
    const float* x0    = (const float*)d_in[0];
    const float* x1    = (const float*)d_in[1];
    const float* hx0   = (const float*)d_in[2];
    const float* hx1   = (const float*)d_in[3];
    const float* W_ih0 = (const float*)d_in[4];
    const float* W_hh0 = (const float*)d_in[5];
    const float* b_ih0 = (const float*)d_in[6];
    const float* b_hh0 = (const float*)d_in[7];
    const float* W_ih1 = (const float*)d_in[8];
    const float* W_hh1 = (const float*)d_in[9];
    const float* b_ih1 = (const float*)d_in[10];
    const float* b_hh1 = (const float*)d_in[11];
    const int*   dx    = (const int*)d_in[12];
    const int*   dxlz  = (const int*)d_in[13];
    float* out = (float*)d_out;

    cudaFuncSetAttribute(persistent_kernel,
                         cudaFuncAttributeMaxDynamicSharedMemorySize, SMEM_BYTES);

    init_state<<<256, 256>>>(hx0, hx1);

    dim3 pgrid(512, 12);
    precompute_kernel<<<pgrid, 256>>>(x0, W_ih0, b_ih0, dx, dxlz, 0);
    precompute_kernel<<<pgrid, 256>>>(x1, W_ih1, b_ih1, dx, dxlz, 1);

    persistent_kernel<<<NCTA, NTHR, SMEM_BYTES>>>(
        W_ih0, W_hh0, b_hh0, W_ih1, W_hh1, b_hh1, dx, dxlz, out);
}

// round 12
// speedup vs baseline: 1.5223x; 1.0015x over previous
#include <cuda_runtime.h>
#include <math.h>

#define BATCH 256
#define TLEN  256
#define HID   256
#define G3    768   // 3*H
#define NCTA  128
#define NTHR  256
#define NPHASE 512

// Scratch (device globals — no allocation)
__device__ float g_gx0[BATCH * TLEN * G3];   // layer0 precomputed gi x-part (+b_ih)
__device__ float g_gx1[BATCH * TLEN * G3];   // layer1
__device__ float g_h0[2][BATCH * HID];       // double-buffered hidden state, parity = t&1
__device__ float g_h1[2][BATCH * HID];
__device__ unsigned g_arrive;
__device__ volatile unsigned g_release;

// ---------------------------------------------------------------------------
__global__ void init_state(const float* __restrict__ hx0, const float* __restrict__ hx1) {
    int i = blockIdx.x * blockDim.x + threadIdx.x;
    if (i == 0) { g_arrive = 0u; g_release = 0u; }
    if (i < BATCH * HID) {
        g_h0[0][i] = hx0[i];
        g_h0[1][i] = hx0[i];
        g_h1[0][i] = hx1[i];
        g_h1[1][i] = hx1[i];
    }
}

// ---------------------------------------------------------------------------
// Precompute: gx[m][j] = mask[m] * sum_k x[m][k]*W[j][k] + b_ih[j]   (unchanged)
// ---------------------------------------------------------------------------
__global__ __launch_bounds__(256) void precompute_kernel(
    const float* __restrict__ x, const float* __restrict__ W,
    const float* __restrict__ bias,
    const int* __restrict__ dx, const int* __restrict__ dxlz, int layer)
{
    __shared__ float As[16][128];
    __shared__ float Bs[16][64];

    float* gx = layer ? g_gx1 : g_gx0;
    int mBase = blockIdx.x * 128;
    int jBase = blockIdx.y * 64;
    int tid = threadIdx.x;
    int tmi = tid & 15;
    int tji = tid >> 4;

    float acc[8][4];
#pragma unroll
    for (int i = 0; i < 8; i++)
#pragma unroll
        for (int j = 0; j < 4; j++) acc[i][j] = 0.0f;

    for (int kk = 0; kk < 256; kk += 16) {
        __syncthreads();
#pragma unroll
        for (int i = 0; i < 2; i++) {
            int idx = tid + i * 256;
            int m   = idx & 127;
            int k4  = idx >> 7;
            int mg  = mBase + m;
            float msk;
            if (layer == 0) msk = (float)dxlz[mg];
            else            msk = (float)dx[((mg >> 8) << 9) + (mg & 255)];
            float4 v = *(const float4*)(x + (size_t)mg * 256 + kk + k4 * 4);
            As[k4 * 4 + 0][m] = v.x * msk;
            As[k4 * 4 + 1][m] = v.y * msk;
            As[k4 * 4 + 2][m] = v.z * msk;
            As[k4 * 4 + 3][m] = v.w * msk;
        }
        {
            int j  = tid & 63;
            int k4 = tid >> 6;
            float4 v = *(const float4*)(W + (size_t)(jBase + j) * 512 + kk + k4 * 4);
            Bs[k4 * 4 + 0][j] = v.x;
            Bs[k4 * 4 + 1][j] = v.y;
            Bs[k4 * 4 + 2][j] = v.z;
            Bs[k4 * 4 + 3][j] = v.w;
        }
        __syncthreads();
#pragma unroll
        for (int k = 0; k < 16; k++) {
            float4 a0 = *(const float4*)&As[k][tmi * 8];
            float4 a1 = *(const float4*)&As[k][tmi * 8 + 4];
            float4 bv = *(const float4*)&Bs[k][tji * 4];
            float am[8] = {a0.x, a0.y, a0.z, a0.w, a1.x, a1.y, a1.z, a1.w};
            float bm[4] = {bv.x, bv.y, bv.z, bv.w};
#pragma unroll
            for (int i = 0; i < 8; i++)
#pragma unroll
                for (int j = 0; j < 4; j++) acc[i][j] += am[i] * bm[j];
        }
    }

    float4 bb = *(const float4*)(bias + jBase + tji * 4);
#pragma unroll
    for (int i = 0; i < 8; i++) {
        int m = mBase + tmi * 8 + i;
        float4 o;
        o.x = acc[i][0] + bb.x;
        o.y = acc[i][1] + bb.y;
        o.z = acc[i][2] + bb.z;
        o.w = acc[i][3] + bb.w;
        *(float4*)(gx + (size_t)m * G3 + jBase + tji * 4) = o;
    }
}

// ---------------------------------------------------------------------------
// Persistent recurrence kernel. 128 CTAs x 256 threads (split-K halves).
// smem: sW 49152 floats (192KB, resident weights, repacked) +
//       sH 2 x 4096 floats (double-buffered h stage / reduction) = 224KB.
// Critical-path ordering per phase:
//   [barrier release] -> load hA chunk0 (hB chunk0 was prefetched pre-barrier)
//   -> GEMM (reg-double-buffered chunks) -> split reduction (both halves)
//   -> epilogue (half outputs each) -> hOut stcg + fence + arrive
//   -> out stores + next-phase hB/epilogue prefetch -> wait release.
// ---------------------------------------------------------------------------
#define SW_SIZE    49152
#define SH_OFF     49152
#define SMEM_BYTES ((SW_SIZE + 8192) * 4)

__device__ __forceinline__ void phase_ptrs(int ph, const float*& hA, const float*& hB,
                                           float*& hOut, const float*& gx) {
    int t = ph >> 1, l = ph & 1, p = t & 1, pn = p ^ 1;
    if (l == 0) { hA = g_h1[p];  hB = g_h0[p]; hOut = g_h0[pn]; gx = g_gx0; }
    else        { hA = g_h0[pn]; hB = g_h1[p]; hOut = g_h1[pn]; gx = g_gx1; }
}

__global__ __launch_bounds__(NTHR, 1) void persistent_kernel(
    const float* __restrict__ Wih0, const float* __restrict__ Whh0,
    const float* __restrict__ bhh0,
    const float* __restrict__ Wih1, const float* __restrict__ Whh1,
    const float* __restrict__ bhh1,
    const int* __restrict__ dx, const int* __restrict__ dxlz,
    float* __restrict__ out)
{
    extern __shared__ float sm[];
    float* sW = sm;
    float* sH = sm + SH_OFF;     // two 4096-float buffers

    int tid   = threadIdx.x;
    int uTile = (blockIdx.x >> 3) * 16;
    int bTile = (blockIdx.x & 7) * 32;
    int half  = tid >> 7;          // split-K half: k in [half*128, half*128+128)
    int t128  = tid & 127;
    int tb = t128 & 15;            // 16 b-threads
    int tu = t128 >> 4;            // 8 u-threads (x2 cols)
    int kBase = half * 128;

    // ---- one-time: stage resident weights (repacked [l][k][u-pair(8)][12]) ----
    for (int i = tid; i < SW_SIZE; i += NTHR) {
        int k  = i & 255;
        int r2 = i >> 12;          // 0..11
        int u  = (i >> 8) & 15;
        int g  = r2 % 3;
        int m  = (r2 / 3) & 1;
        int l  = r2 / 6;
        int row = g * 256 + uTile + u;
        float v;
        if (m == 0) {
            const float* W = l ? Wih1 : Wih0;
            v = W[(size_t)row * 512 + 256 + k];
        } else {
            const float* W = l ? Whh1 : Whh0;
            v = W[(size_t)row * 256 + k];
        }
        sW[((l * 256 + k) * 8 + (u >> 1)) * 12 + m * 6 + g * 2 + (u & 1)] = v;
    }

    // ---- biases in registers (all threads; epilogue is split across halves) ----
    float rb0g[3][2], rb1g[3][2];
#pragma unroll
    for (int g = 0; g < 3; g++)
#pragma unroll
        for (int ui = 0; ui < 2; ui++) {
            int u = g * 256 + uTile + tu * 2 + ui;
            rb0g[g][ui] = bhh0[u];
            rb1g[g][ui] = bhh1[u];
        }
    __syncthreads();

    // staging geometry
    int b_s = t128 & 31;
    int k4base = (t128 >> 5);      // 0..3
    const size_t hOffA = (size_t)(bTile + b_s) * HID + kBase + k4base * 4;
    const size_t hOffB = (size_t)(bTile + b_s) * HID + kBase + (k4base + 4) * 4;
    int bMine = bTile + tb * 2 + half;   // this thread's epilogue batch row
    int uMine = uTile + tu * 2;
    int keepBase = half * 6;             // acc base for this thread's bi(=half)
    int sendBase = 6 - keepBase;         // acc base shipped to the other half

    // ---- prologue: prefetch phase 0 operands ----
    float4 rnb0, rnb1;                    // next-phase hB chunk0
    float pgx[3][2], phb[2], mAv, fBv;
    int byp;
    {
        const float *hA, *hB, *gx; float* hOut;
        phase_ptrs(0, hA, hB, hOut, gx);
        rnb0 = __ldcg((const float4*)(hB + hOffA));
        rnb1 = __ldcg((const float4*)(hB + hOffB));
        int b0  = dxlz[bMine * TLEN + 0];
        mAv = 0.0f; fBv = 1.0f; byp = (b0 == 0);
        const float* gxr = gx + (size_t)(bMine * TLEN + 0) * G3;
        float2 v0 = __ldcg((const float2*)(gxr + uMine));
        float2 v1 = __ldcg((const float2*)(gxr + 256 + uMine));
        float2 v2 = __ldcg((const float2*)(gxr + 512 + uMine));
        pgx[0][0] = v0.x; pgx[0][1] = v0.y;
        pgx[1][0] = v1.x; pgx[1][1] = v1.y;
        pgx[2][0] = v2.x; pgx[2][1] = v2.y;
        float2 hv = __ldcg((const float2*)(hB + (size_t)bMine * HID + uMine));
        phb[0] = hv.x; phb[1] = hv.y;
    }

#pragma unroll 1
    for (int ph = 0; ph < NPHASE; ph++) {
        int t = ph >> 1, l = ph & 1;
        const float *hA, *hB, *gx; float* hOut;
        phase_ptrs(ph, hA, hB, hOut, gx);

        // ---- post-barrier: load fresh hA chunk0, stage chunk0 to buf0 ----
        float4 ra0 = __ldcg((const float4*)(hA + hOffA));
        float4 ra1 = __ldcg((const float4*)(hA + hOffB));
        {
            float* base = sH + half * 2048;
            float* dA0 = base + (k4base * 4) * 32 + b_s;
            float* dA1 = base + ((k4base + 4) * 4) * 32 + b_s;
            float* dB0 = dA0 + 1024;
            float* dB1 = dA1 + 1024;
            dA0[0]=ra0.x;  dA0[32]=ra0.y;  dA0[64]=ra0.z;  dA0[96]=ra0.w;
            dA1[0]=ra1.x;  dA1[32]=ra1.y;  dA1[64]=ra1.z;  dA1[96]=ra1.w;
            dB0[0]=rnb0.x; dB0[32]=rnb0.y; dB0[64]=rnb0.z; dB0[96]=rnb0.w;
            dB1[0]=rnb1.x; dB1[32]=rnb1.y; dB1[64]=rnb1.z; dB1[96]=rnb1.w;
        }
        __syncthreads();

        float acc[24];
#pragma unroll
        for (int j = 0; j < 24; j++) acc[j] = 0.0f;

        float4 rg[4];
#pragma unroll 1
        for (int c = 0; c < 4; c++) {
            if (c < 3) {
                int koff = (c + 1) * 32;
                rg[0] = __ldcg((const float4*)(hA + hOffA + koff));
                rg[1] = __ldcg((const float4*)(hA + hOffB + koff));
                rg[2] = __ldcg((const float4*)(hB + hOffA + koff));
                rg[3] = __ldcg((const float4*)(hB + hOffB + koff));
            }
            const float* sa = sH + (c & 1) * 4096 + half * 2048;
            const float* sb = sa + 1024;
            const float* wbase = sW + ((size_t)(l * 256 + kBase + c * 32) * 8 + tu) * 12;
#pragma unroll
            for (int k = 0; k < 32; k++) {
                float2 a  = *(const float2*)(sa + k * 32 + tb * 2);
                float2 hb = *(const float2*)(sb + k * 32 + tb * 2);
                const float* w = wbase + k * 96;
                float4 wA = *(const float4*)(w);
                float4 wB = *(const float4*)(w + 4);
                float4 wC = *(const float4*)(w + 8);
                acc[0]  += a.x * wA.x;  acc[3]  += a.x * wA.y;
                acc[6]  += a.y * wA.x;  acc[9]  += a.y * wA.y;
                acc[1]  += a.x * wA.z;  acc[4]  += a.x * wA.w;
                acc[7]  += a.y * wA.z;  acc[10] += a.y * wA.w;
                acc[2]  += a.x * wB.x;  acc[5]  += a.x * wB.y;
                acc[8]  += a.y * wB.x;  acc[11] += a.y * wB.y;
                acc[12] += hb.x * wB.z; acc[15] += hb.x * wB.w;
                acc[18] += hb.y * wB.z; acc[21] += hb.y * wB.w;
                acc[13] += hb.x * wC.x; acc[16] += hb.x * wC.y;
                acc[19] += hb.y * wC.x; acc[22] += hb.y * wC.y;
                acc[14] += hb.x * wC.z; acc[17] += hb.x * wC.w;
                acc[20] += hb.y * wC.z; acc[23] += hb.y * wC.w;
            }
            if (c < 3) {
                float* base = sH + ((c + 1) & 1) * 4096 + half * 2048;
                float* dA0 = base + (k4base * 4) * 32 + b_s;
                float* dA1 = base + ((k4base + 4) * 4) * 32 + b_s;
                float* dB0 = dA0 + 1024;
                float* dB1 = dA1 + 1024;
                dA0[0]=rg[0].x; dA0[32]=rg[0].y; dA0[64]=rg[0].z; dA0[96]=rg[0].w;
                dA1[0]=rg[1].x; dA1[32]=rg[1].y; dA1[64]=rg[1].z; dA1[96]=rg[1].w;
                dB0[0]=rg[2].x; dB0[32]=rg[2].y; dB0[64]=rg[2].z; dB0[96]=rg[2].w;
                dB1[0]=rg[3].x; dB1[32]=rg[3].y; dB1[64]=rg[3].z; dB1[96]=rg[3].w;
                __syncthreads();
            }
        }

        // ---- split-K exchange: each half ships the other half's bi partials ----
        // (chunk-3 compute reads buf1; sRed lives in buf0 — disjoint, no sync needed)
        float* sRed = sH;                       // 2 x 1536 floats in buf0
        {
            float* wr = sRed + half * 1536 + t128 * 12;
#pragma unroll
            for (int j = 0; j < 6; j++) {
                wr[j]     = acc[sendBase + j];
                wr[6 + j] = acc[12 + sendBase + j];
            }
        }
        __syncthreads();
        {
            const float* rd = sRed + (half ^ 1) * 1536 + t128 * 12;
#pragma unroll
            for (int j = 0; j < 6; j++) {
                acc[keepBase + j]      += rd[j];
                acc[12 + keepBase + j] += rd[6 + j];
            }
        }

        // ---- epilogue: this thread's single batch row, 2 u outputs ----
        float res2[2];
#pragma unroll
        for (int ui = 0; ui < 2; ui++) {
            int ai = keepBase + ui * 3;
            float hUsed = phb[ui] * fBv;
            float giR = pgx[0][ui] + mAv * acc[ai + 0];
            float giZ = pgx[1][ui] + mAv * acc[ai + 1];
            float giN = pgx[2][ui] + mAv * acc[ai + 2];
            float bR = l ? rb1g[0][ui] : rb0g[0][ui];
            float bZ = l ? rb1g[1][ui] : rb0g[1][ui];
            float bN = l ? rb1g[2][ui] : rb0g[2][ui];
            float ghR = bR + fBv * acc[12 + ai + 0];
            float ghZ = bZ + fBv * acc[12 + ai + 1];
            float ghN = bN + fBv * acc[12 + ai + 2];
            float r = 1.0f / (1.0f + expf(-(giR + ghR)));
            float z = 1.0f / (1.0f + expf(-(giZ + ghZ)));
            float n = tanhf(giN + r * ghN);
            float hnew = (1.0f - z) * n + z * hUsed;
            res2[ui] = byp ? hUsed : hnew;
        }
        float2 rv; rv.x = res2[0]; rv.y = res2[1];
        __stcg((float2*)(hOut + (size_t)bMine * HID + uMine), rv);

        // ---- arrive ASAP; defer out-store + prefetch to the wait window ----
        __threadfence();
        __syncthreads();
        unsigned target = (unsigned)(ph + 1);
        if (tid == 0) {
            unsigned v = atomicAdd(&g_arrive, 1u) + 1u;
            if (v == (unsigned)NCTA * target) g_release = target;
        }

        __stcg((float2*)(out + (((size_t)l * BATCH + bMine) * TLEN + t) * HID + uMine), rv);

        if (ph + 1 < NPHASE) {
            int q = ph + 1, tq = q >> 1, lq = q & 1;
            const float *hAq, *hBq, *gxq; float* hOq;
            phase_ptrs(q, hAq, hBq, hOq, gxq);
            rnb0 = __ldcg((const float4*)(hBq + hOffA));
            rnb1 = __ldcg((const float4*)(hBq + hOffB));
            if (lq == 0) {
                int b0  = dxlz[bMine * TLEN + tq];
                int dd0 = dx[(bMine * 2) * TLEN + tq - 1];
                mAv = (float)dd0; fBv = 1.0f - (float)dd0; byp = (b0 + dd0 == 0);
            } else {
                int b1  = dx[(bMine * 2) * TLEN + tq];
                int dd1 = (tq > 0) ? dx[(bMine * 2 + 1) * TLEN + tq - 1] : 0;
                mAv = (float)b1; fBv = 1.0f - (float)dd1; byp = (b1 + dd1 == 0);
            }
            const float* gxr = gxq + (size_t)(bMine * TLEN + tq) * G3;
            float2 v0 = __ldcg((const float2*)(gxr + uMine));
            float2 v1 = __ldcg((const float2*)(gxr + 256 + uMine));
            float2 v2 = __ldcg((const float2*)(gxr + 512 + uMine));
            pgx[0][0] = v0.x; pgx[0][1] = v0.y;
            pgx[1][0] = v1.x; pgx[1][1] = v1.y;
            pgx[2][0] = v2.x; pgx[2][1] = v2.y;
            float2 hv = __ldcg((const float2*)(hBq + (size_t)bMine * HID + uMine));
            phb[0] = hv.x; phb[1] = hv.y;

            if (tid == 0) {
                while (g_release < target) __nanosleep(32);
            }
            __syncthreads();
        }
    }
}

// ---------------------------------------------------------------------------
extern "C" void kernel_launch(void* const* d_in, const int* in_sizes, int n_in,
                              void* d_out, int out_size) {
    const float* x0    = (const float*)d_in[0];
    const float* x1    = (const float*)d_in[1];
    const float* hx0   = (const float*)d_in[2];
    const float* hx1   = (const float*)d_in[3];
    const float* W_ih0 = (const float*)d_in[4];
    const float* W_hh0 = (const float*)d_in[5];
    const float* b_ih0 = (const float*)d_in[6];
    const float* b_hh0 = (const float*)d_in[7];
    const float* W_ih1 = (const float*)d_in[8];
    const float* W_hh1 = (const float*)d_in[9];
    const float* b_ih1 = (const float*)d_in[10];
    const float* b_hh1 = (const float*)d_in[11];
    const int*   dx    = (const int*)d_in[12];
    const int*   dxlz  = (const int*)d_in[13];
    float* out = (float*)d_out;

    cudaFuncSetAttribute(persistent_kernel,
                         cudaFuncAttributeMaxDynamicSharedMemorySize, SMEM_BYTES);

    init_state<<<256, 256>>>(hx0, hx1);

    dim3 pgrid(512, 12);
    precompute_kernel<<<pgrid, 256>>>(x0, W_ih0, b_ih0, dx, dxlz, 0);
    precompute_kernel<<<pgrid, 256>>>(x1, W_ih1, b_ih1, dx, dxlz, 1);

    persistent_kernel<<<NCTA, NTHR, SMEM_BYTES>>>(
        W_ih0, W_hh0, b_hh0, W_ih1, W_hh1, b_hh1, dx, dxlz, out);
}